// round 8
// baseline (speedup 1.0000x reference)
#include <cuda_runtime.h>
#include <cstdint>
#include <cstddef>

#define NB   32
#define NS   512
#define ND   512
#define NH2  256
#define NG3  768
#define NDK  64

// ------------------------- scratch (device globals) -------------------------
__device__ float g_xg[(size_t)2 * NB * NS * NG3];   // gate preactivations, per dir
__device__ float g_gru[(size_t)NB * NS * ND];       // concat GRU outputs
__device__ float g_ln1[(size_t)NB * NS * ND];       // ln1("outputs")
__device__ float g_q [(size_t)NB * 8 * NS * NDK];   // (b,h,s,d)
__device__ float g_k [(size_t)NB * 8 * NS * NDK];   // (b,h,s,d)
__device__ float g_vt[(size_t)NB * 8 * NDK * NS];   // (b,h,d,s)
__device__ float g_sc[(size_t)NB * 8 * NS * NS];    // scores -> p
__device__ float g_cc[(size_t)NB * NS * ND];        // attn concat
__device__ float g_o [(size_t)NB * NS * ND];        // out projection

// ------------------------- f32x2 helpers -------------------------
__device__ __forceinline__ unsigned long long fma2(unsigned long long a,
                                                   unsigned long long b,
                                                   unsigned long long c) {
    unsigned long long d;
    asm("fma.rn.f32x2 %0, %1, %2, %3;" : "=l"(d) : "l"(a), "l"(b), "l"(c));
    return d;
}
__device__ __forceinline__ unsigned long long pack2(float x, float y) {
    unsigned long long d;
    asm("mov.b64 %0, {%1, %2};" : "=l"(d) : "f"(x), "f"(y));
    return d;
}
__device__ __forceinline__ void unpack2(unsigned long long v, float& x, float& y) {
    asm("mov.b64 {%0, %1}, %2;" : "=f"(x), "=f"(y) : "l"(v));
}
__device__ __forceinline__ float tf32r(float f) {
    unsigned u;
    asm("cvt.rna.tf32.f32 %0, %1;" : "=r"(u) : "f"(f));
    return __uint_as_float(u);
}

// ------------------------- epilogue store -------------------------
// modes:
// 0: +bias              1: +bias, scatter (b,h,s,d)   2: +bias, scatter (b,h,d,s)
// 3: *scale             4: scatter concat (b,s,h*64+d) 5: +bias, *rowmask(masks)
__device__ __forceinline__ void store_elem(float* C, const float* bias,
                                           const int* masks, int mode, float scale,
                                           int z, int N, int mrow, int nc, float v) {
    if (nc >= N) return;
    if (mode == 0) {
        C[(long)mrow * N + nc] = v + bias[nc];
    } else if (mode == 1) {
        int b = mrow >> 9, s = mrow & 511, h = nc >> 6, d = nc & 63;
        C[(((long)(b * 8 + h) * NS + s)) * NDK + d] = v + bias[nc];
    } else if (mode == 2) {
        int b = mrow >> 9, s = mrow & 511, h = nc >> 6, d = nc & 63;
        C[((long)(b * 8 + h) * NDK + d) * NS + s] = v + bias[nc];
    } else if (mode == 3) {
        C[(long)mrow * N + nc] = v * scale;
    } else if (mode == 4) {
        int b = z >> 3, h = z & 7;
        C[((long)(b * NS + mrow)) * ND + h * NDK + nc] = v;
    } else {
        C[(long)mrow * N + nc] = masks[mrow] ? (v + bias[nc]) : 0.f;
    }
}

// ------------------------- tf32 tensor-core TN GEMM -------------------------
// C = epi(A[M,K] @ W[N,K]^T) via mma.sync.m16n8k8 tf32.
// 128x128x16 tile, 256 thr = 8 warps (2x4), each warp 64x32.
__global__ void __launch_bounds__(256) gemm_tf32(
    const float* __restrict__ A, const float* __restrict__ W,
    const float* __restrict__ bias, float* __restrict__ C,
    int M, int N, int K, long sA, long sW, long sC,
    int mode, float scale, const int* __restrict__ masks)
{
    __shared__ float As[128][20];   // [m][k], pad 20 -> conflict-free frag loads
    __shared__ float Ws[128][20];   // [n][k]

    const int z = blockIdx.z;
    A += (long)z * sA;
    W += (long)z * sW;
    if (mode == 3) C += (long)z * sC;

    const int m0 = blockIdx.y * 128, n0 = blockIdx.x * 128;
    const int tid  = threadIdx.x;
    const int warp = tid >> 5, lane = tid & 31;
    const int wm = warp >> 2, wn = warp & 3;   // warp grid 2 x 4
    const int g  = lane >> 2, tg = lane & 3;   // mma group / thread-in-group

    const int lm = tid >> 2, lkq = tid & 3;
    const float* Aip = A + (long)(m0 + lm) * K + lkq * 4;
    const float* Wip = W + (long)(n0 + lm) * K + lkq * 4;
    const bool w0ok = (n0 + lm) < N;
    const bool w1ok = (n0 + lm + 64) < N;
    const float4 z4 = make_float4(0.f, 0.f, 0.f, 0.f);

    float acc[4][4][4];
#pragma unroll
    for (int mt = 0; mt < 4; mt++)
#pragma unroll
        for (int nt = 0; nt < 4; nt++)
#pragma unroll
            for (int c = 0; c < 4; c++) acc[mt][nt][c] = 0.f;

    float4 a0v = *(const float4*)Aip;
    float4 a1v = *(const float4*)(Aip + (long)64 * K);
    float4 w0v = w0ok ? *(const float4*)Wip : z4;
    float4 w1v = w1ok ? *(const float4*)(Wip + (long)64 * K) : z4;

    for (int k0 = 0; k0 < K; k0 += 16) {
        __syncthreads();
        {
            float* pa0 = &As[lm][lkq * 4];
            pa0[0] = tf32r(a0v.x); pa0[1] = tf32r(a0v.y);
            pa0[2] = tf32r(a0v.z); pa0[3] = tf32r(a0v.w);
            float* pa1 = &As[lm + 64][lkq * 4];
            pa1[0] = tf32r(a1v.x); pa1[1] = tf32r(a1v.y);
            pa1[2] = tf32r(a1v.z); pa1[3] = tf32r(a1v.w);
            float* pw0 = &Ws[lm][lkq * 4];
            pw0[0] = tf32r(w0v.x); pw0[1] = tf32r(w0v.y);
            pw0[2] = tf32r(w0v.z); pw0[3] = tf32r(w0v.w);
            float* pw1 = &Ws[lm + 64][lkq * 4];
            pw1[0] = tf32r(w1v.x); pw1[1] = tf32r(w1v.y);
            pw1[2] = tf32r(w1v.z); pw1[3] = tf32r(w1v.w);
        }
        __syncthreads();
        if (k0 + 16 < K) {
            a0v = *(const float4*)(Aip + k0 + 16);
            a1v = *(const float4*)(Aip + (long)64 * K + k0 + 16);
            w0v = w0ok ? *(const float4*)(Wip + k0 + 16) : z4;
            w1v = w1ok ? *(const float4*)(Wip + (long)64 * K + k0 + 16) : z4;
        }
#pragma unroll
        for (int kb = 0; kb < 2; kb++) {
            const int kk = kb * 8 + tg;
            unsigned a[4][4], b[4][2];
#pragma unroll
            for (int mt = 0; mt < 4; mt++) {
                const int rm = wm * 64 + mt * 16 + g;
                a[mt][0] = __float_as_uint(As[rm][kk]);
                a[mt][1] = __float_as_uint(As[rm + 8][kk]);
                a[mt][2] = __float_as_uint(As[rm][kk + 4]);
                a[mt][3] = __float_as_uint(As[rm + 8][kk + 4]);
            }
#pragma unroll
            for (int nt = 0; nt < 4; nt++) {
                const int rn = wn * 32 + nt * 8 + g;
                b[nt][0] = __float_as_uint(Ws[rn][kk]);
                b[nt][1] = __float_as_uint(Ws[rn][kk + 4]);
            }
#pragma unroll
            for (int mt = 0; mt < 4; mt++)
#pragma unroll
                for (int nt = 0; nt < 4; nt++) {
                    asm volatile(
                        "mma.sync.aligned.m16n8k8.row.col.f32.tf32.tf32.f32 "
                        "{%0,%1,%2,%3}, {%4,%5,%6,%7}, {%8,%9}, {%0,%1,%2,%3};"
                        : "+f"(acc[mt][nt][0]), "+f"(acc[mt][nt][1]),
                          "+f"(acc[mt][nt][2]), "+f"(acc[mt][nt][3])
                        : "r"(a[mt][0]), "r"(a[mt][1]), "r"(a[mt][2]), "r"(a[mt][3]),
                          "r"(b[nt][0]), "r"(b[nt][1]));
                }
        }
    }

#pragma unroll
    for (int mt = 0; mt < 4; mt++) {
#pragma unroll
        for (int nt = 0; nt < 4; nt++) {
            const int row0 = m0 + wm * 64 + mt * 16 + g;
            const int col0 = n0 + wn * 32 + nt * 8 + 2 * tg;
            store_elem(C, bias, masks, mode, scale, z, N, row0,     col0,     acc[mt][nt][0]);
            store_elem(C, bias, masks, mode, scale, z, N, row0,     col0 + 1, acc[mt][nt][1]);
            store_elem(C, bias, masks, mode, scale, z, N, row0 + 8, col0,     acc[mt][nt][2]);
            store_elem(C, bias, masks, mode, scale, z, N, row0 + 8, col0 + 1, acc[mt][nt][3]);
        }
    }
}

// ------------------------- persistent GRU (cluster DSMEM push + mbarrier) ---
// 128 blocks = 16 clusters of 8. cluster = (dir, batchgroup of 4 batches),
// rank jc in [0,8) owns 32 j (96 gate rows). 384 threads =
// rg(48, 2 gate-rows) x ks(8, 32-k slice); weights register-resident.
// h in smem, double-buffered, XOR-swizzled (chunk (ks<<3)|(i^ks)).
// Updaters PUSH h directly into all 8 ranks' sh_h[(t+1)&1] via
// st.shared::cluster; each updater warp's lane0 arrives (release.cluster)
// on all 8 ranks' mbarriers (count 8 ranks x 4 warps = 32); consumers do one
// try_wait.parity.acquire.cluster per step. NO barrier.cluster in the loop
// (round-3 lesson: it emits CCTL.IVALL -> L1D flush every step).
__global__ void __launch_bounds__(384, 1) __cluster_dims__(8, 1, 1)
gru_kernel(
    const float* __restrict__ whf, const float* __restrict__ whb,
    const float* __restrict__ bhf, const float* __restrict__ bhb,
    const int* __restrict__ masks, float* __restrict__ hid_out)
{
    __shared__ float sh_h[2][1024];  // [buf][b][swizzled k], 4 batches
    __shared__ float sh_gate[384];   // [row][b]
    __shared__ __align__(8) unsigned long long sh_mbar[1];

    const int bid = blockIdx.x;
    const int jc  = bid & 7;         // cluster rank == j-chunk
    const int cl  = bid >> 3;
    const int dir = cl >> 3;
    const int bg  = cl & 7;
    const int tid = threadIdx.x;
    const int rg  = tid >> 3;        // 0..47 (gate-row pair)
    const int ks  = tid & 7;         // k eighth (32 values)
    const int row0 = rg * 2, row1 = rg * 2 + 1;
    const int G0 = (row0 >> 5) * 256 + jc * 32 + (row0 & 31);
    const int G1 = (row1 >> 5) * 256 + jc * 32 + (row1 & 31);

    const float* wh = dir ? whb : whf;
    const float* bh = dir ? bhb : bhf;
    const float bh0 = bh[G0], bh1 = bh[G1];

    unsigned long long wp0[16], wp1[16];
    {
        const float* w0s = wh + (long)G0 * NH2 + ks * 32;
        const float* w1s = wh + (long)G1 * NH2 + ks * 32;
#pragma unroll
        for (int i = 0; i < 16; i++) {
            wp0[i] = pack2(w0s[2 * i], w0s[2 * i + 1]);
            wp1[i] = pack2(w1s[2 * i], w1s[2 * i + 1]);
        }
    }

    const int ju = tid & 31, bu = tid >> 5;   // updater role (tid < 128)
    const int jglob = jc * 32 + ju;
    const int bglob = bg * 4 + bu;
    const float* xgp = g_xg + ((size_t)dir * NB + bglob) * NS * NG3;

    // cluster addresses
    const uint32_t shbase = (uint32_t)__cvta_generic_to_shared(&sh_h[0][0]);
    const uint32_t mbaddr = (uint32_t)__cvta_generic_to_shared(sh_mbar);
    uint32_t rb[8], ab[8];
#pragma unroll
    for (int rk = 0; rk < 8; rk++) {
        asm("mapa.shared::cluster.u32 %0, %1, %2;" : "=r"(rb[rk]) : "r"(shbase), "r"(rk));
        asm("mapa.shared::cluster.u32 %0, %1, %2;" : "=r"(ab[rk]) : "r"(mbaddr), "r"(rk));
    }
    // updater's swizzled byte offset inside a buffer
    const uint32_t upoff =
        (uint32_t)((bu * 256 + (jc * 8 + ((ju >> 2) ^ jc)) * 4 + (ju & 3)) * 4);

    if (tid == 0) {
        asm volatile("mbarrier.init.shared.b64 [%0], %1;"
                     :: "r"(mbaddr), "r"(32u) : "memory");
    }
    for (int i = tid; i < 2048; i += 384) sh_h[0][i] = 0.f;
    float hreg = 0.f;
    // one-time: mbarrier init + smem zero visible cluster-wide
    asm volatile("barrier.cluster.arrive.aligned;" ::: "memory");
    asm volatile("barrier.cluster.wait.aligned;"   ::: "memory");

    for (int t = 0; t < NS; t++) {
        const int s = dir ? (NS - 1 - t) : t;
        float xr = 0.f, xz = 0.f, xn = 0.f;
        int mk = 0;
        if (tid < 128) {  // prefetch x-gates + mask (independent of h)
            const float* xrow = xgp + (size_t)s * NG3;
            xr = __ldg(xrow + jglob);
            xz = __ldg(xrow + NH2 + jglob);
            xn = __ldg(xrow + 2 * NH2 + jglob);
            mk = __ldg(masks + bglob * NS + s);
        }
        if (t > 0) {
            const unsigned par = (unsigned)((t - 1) & 1);
            asm volatile(
                "{\n\t.reg .pred P;\n\t"
                "WAIT%=:\n\t"
                "mbarrier.try_wait.parity.acquire.cluster.shared::cta.b64 P, [%0], %1, 0x989680;\n\t"
                "@!P bra WAIT%=;\n\t}"
                :: "r"(mbaddr), "r"(par) : "memory");
        }
        // gate dot products from sh_h[t&1]: 2 gate-rows x 4 batches
        const float* hp = sh_h[t & 1];
        unsigned long long a0[4] = {0ull, 0ull, 0ull, 0ull};
        unsigned long long a1[4] = {0ull, 0ull, 0ull, 0ull};
#pragma unroll
        for (int i = 0; i < 8; i++) {
            const int coff = (((ks << 3) | (i ^ ks)) << 2);
#pragma unroll
            for (int b = 0; b < 4; b++) {
                ulonglong2 hv = *(const ulonglong2*)(hp + b * 256 + coff);
                a0[b] = fma2(wp0[2 * i],     hv.x, a0[b]);
                a0[b] = fma2(wp0[2 * i + 1], hv.y, a0[b]);
                a1[b] = fma2(wp1[2 * i],     hv.x, a1[b]);
                a1[b] = fma2(wp1[2 * i + 1], hv.y, a1[b]);
            }
        }
        float v0[4], v1[4];
#pragma unroll
        for (int b = 0; b < 4; b++) {
            float lo, hi;
            unpack2(a0[b], lo, hi); v0[b] = lo + hi;
            unpack2(a1[b], lo, hi); v1[b] = lo + hi;
        }
#pragma unroll
        for (int off = 1; off < 8; off <<= 1) {
#pragma unroll
            for (int b = 0; b < 4; b++) {
                v0[b] += __shfl_xor_sync(~0u, v0[b], off);
                v1[b] += __shfl_xor_sync(~0u, v1[b], off);
            }
        }
        if (ks == 0) {
            float4 f0 = make_float4(v0[0] + bh0, v0[1] + bh0, v0[2] + bh0, v0[3] + bh0);
            float4 f1 = make_float4(v1[0] + bh1, v1[1] + bh1, v1[2] + bh1, v1[3] + bh1);
            *(float4*)&sh_gate[rg * 8]     = f0;
            *(float4*)&sh_gate[rg * 8 + 4] = f1;
        }
        __syncthreads();   // gates ready; also: ALL reads of sh_h[t&1] done
        if (tid < 128) {
            const float hgr = sh_gate[ju * 4 + bu];
            const float hgz = sh_gate[(32 + ju) * 4 + bu];
            const float hgn = sh_gate[(64 + ju) * 4 + bu];
            const float rr = 1.f / (1.f + __expf(-(xr + hgr)));
            const float zz = 1.f / (1.f + __expf(-(xz + hgz)));
            const float na = xn + rr * hgn;
            const float nn = 2.f / (1.f + __expf(-2.f * na)) - 1.f;  // tanh
            const float hnew = (1.f - zz) * nn + zz * hreg;
            hreg = mk ? hnew : hreg;
            g_gru[((size_t)bglob * NS + s) * ND + dir * NH2 + jglob] = mk ? hreg : 0.f;
            if (t == NS - 1) {
                hid_out[bglob * ND + dir * NH2 + jglob] = hreg;
            } else {
                const uint32_t boff = ((unsigned)((t + 1) & 1)) * 4096u + upoff;
#pragma unroll
                for (int rk = 0; rk < 8; rk++) {
                    asm volatile("st.shared::cluster.f32 [%0], %1;"
                                 :: "r"(rb[rk] + boff), "f"(hreg) : "memory");
                }
                __syncwarp();
                if (ju == 0) {
#pragma unroll
                    for (int rk = 0; rk < 8; rk++) {
                        asm volatile("mbarrier.arrive.release.cluster.shared::cluster.b64 _, [%0];"
                                     :: "r"(ab[rk]) : "memory");
                    }
                }
            }
        }
    }
    // exit safety: no CTA leaves while peers may still touch its smem
    asm volatile("barrier.cluster.arrive.aligned;" ::: "memory");
    asm volatile("barrier.cluster.wait.aligned;"   ::: "memory");
}

// ------------------------- layernorm (optionally fused residual) -------------------------
__global__ void __launch_bounds__(128) ln_kernel(
    const float* __restrict__ x, const float* __restrict__ y,
    const float* __restrict__ gam, const float* __restrict__ bet,
    float* __restrict__ out)
{
    __shared__ float red[8];
    const int row = blockIdx.x;
    const int tid = threadIdx.x;
    float4 v = *(const float4*)(x + (size_t)row * ND + tid * 4);
    if (y) {
        float4 w = *(const float4*)(y + (size_t)row * ND + tid * 4);
        v.x += w.x; v.y += w.y; v.z += w.z; v.w += w.w;
    }
    float s1 = v.x + v.y + v.z + v.w;
    float s2 = v.x * v.x + v.y * v.y + v.z * v.z + v.w * v.w;
#pragma unroll
    for (int o = 16; o; o >>= 1) {
        s1 += __shfl_xor_sync(~0u, s1, o);
        s2 += __shfl_xor_sync(~0u, s2, o);
    }
    const int wid = tid >> 5;
    if ((tid & 31) == 0) { red[wid] = s1; red[wid + 4] = s2; }
    __syncthreads();
    s1 = red[0] + red[1] + red[2] + red[3];
    s2 = red[4] + red[5] + red[6] + red[7];
    const float mu = s1 * (1.f / ND);
    const float var = s2 * (1.f / ND) - mu * mu;
    const float rs = rsqrtf(var + 1e-5f);
    const float4 gv = *(const float4*)(gam + tid * 4);
    const float4 bv = *(const float4*)(bet + tid * 4);
    float4 o4;
    o4.x = (v.x - mu) * rs * gv.x + bv.x;
    o4.y = (v.y - mu) * rs * gv.y + bv.y;
    o4.z = (v.z - mu) * rs * gv.z + bv.z;
    o4.w = (v.w - mu) * rs * gv.w + bv.w;
    *(float4*)(out + (size_t)row * ND + tid * 4) = o4;
}

// ------------------------- masked prefix softmax -------------------------
__global__ void __launch_bounds__(128) softmax_kernel(
    float* __restrict__ P, const int* __restrict__ lengths)
{
    __shared__ float red[4];
    const int q = blockIdx.x, z = blockIdx.y;
    const int len = __ldg(lengths + (z >> 3));
    float* row = P + ((size_t)z * NS + q) * NS;
    const int tid = threadIdx.x;
    const int c0 = tid * 4;
    if (q >= len) {
        *(float4*)(row + c0) = make_float4(0.f, 0.f, 0.f, 0.f);
        return;
    }
    float4 v = *(const float4*)(row + c0);
    const bool b0 = c0 < len, b1 = c0 + 1 < len, b2 = c0 + 2 < len, b3 = c0 + 3 < len;
    float m = -1e30f;
    if (b0) m = fmaxf(m, v.x);
    if (b1) m = fmaxf(m, v.y);
    if (b2) m = fmaxf(m, v.z);
    if (b3) m = fmaxf(m, v.w);
#pragma unroll
    for (int o = 16; o; o >>= 1) m = fmaxf(m, __shfl_xor_sync(~0u, m, o));
    const int wid = tid >> 5;
    if ((tid & 31) == 0) red[wid] = m;
    __syncthreads();
    m = fmaxf(fmaxf(red[0], red[1]), fmaxf(red[2], red[3]));
    __syncthreads();
    float4 e;
    e.x = b0 ? __expf(v.x - m) : 0.f;
    e.y = b1 ? __expf(v.y - m) : 0.f;
    e.z = b2 ? __expf(v.z - m) : 0.f;
    e.w = b3 ? __expf(v.w - m) : 0.f;
    float s = e.x + e.y + e.z + e.w;
#pragma unroll
    for (int o = 16; o; o >>= 1) s += __shfl_xor_sync(~0u, s, o);
    if ((tid & 31) == 0) red[wid] = s;
    __syncthreads();
    s = red[0] + red[1] + red[2] + red[3];
    const float inv = 1.f / s;
    e.x *= inv; e.y *= inv; e.z *= inv; e.w *= inv;
    *(float4*)(row + c0) = e;
}

// ------------------------- launch -------------------------
extern "C" void kernel_launch(void* const* d_in, const int* in_sizes, int n_in,
                              void* d_out, int out_size)
{
    const float* splits = (const float*)d_in[0];
    const float* w_ih_f = (const float*)d_in[1];
    const float* w_hh_f = (const float*)d_in[2];
    const float* b_ih_f = (const float*)d_in[3];
    const float* b_hh_f = (const float*)d_in[4];
    const float* w_ih_b = (const float*)d_in[5];
    const float* w_hh_b = (const float*)d_in[6];
    const float* b_ih_b = (const float*)d_in[7];
    const float* b_hh_b = (const float*)d_in[8];
    const float* ln1_g  = (const float*)d_in[9];
    const float* ln1_b  = (const float*)d_in[10];
    const float* wq = (const float*)d_in[11];
    const float* bq = (const float*)d_in[12];
    const float* wk = (const float*)d_in[13];
    const float* bk = (const float*)d_in[14];
    const float* wv = (const float*)d_in[15];
    const float* bv = (const float*)d_in[16];
    const float* wo = (const float*)d_in[17];
    const float* bo = (const float*)d_in[18];
    const float* ln2_g = (const float*)d_in[19];
    const float* ln2_b = (const float*)d_in[20];
    const int* lengths = (const int*)d_in[21];
    const int* masks   = (const int*)d_in[22];
    float* out = (float*)d_out;

    float *xg, *gru, *ln1, *q, *k, *vt, *sc, *cc, *oo;
    cudaGetSymbolAddress((void**)&xg,  g_xg);
    cudaGetSymbolAddress((void**)&gru, g_gru);
    cudaGetSymbolAddress((void**)&ln1, g_ln1);
    cudaGetSymbolAddress((void**)&q,   g_q);
    cudaGetSymbolAddress((void**)&k,   g_k);
    cudaGetSymbolAddress((void**)&vt,  g_vt);
    cudaGetSymbolAddress((void**)&sc,  g_sc);
    cudaGetSymbolAddress((void**)&cc,  g_cc);
    cudaGetSymbolAddress((void**)&oo,  g_o);

    const int M = NB * NS;  // 16384

    // GRU input projections (both dirs) — tf32 tensor cores
    gemm_tf32<<<dim3(6, 128, 1), 256>>>(splits, w_ih_f, b_ih_f, xg,
                                        M, NG3, ND, 0, 0, 0, 0, 1.f, nullptr);
    gemm_tf32<<<dim3(6, 128, 1), 256>>>(splits, w_ih_b, b_ih_b, xg + (size_t)M * NG3,
                                        M, NG3, ND, 0, 0, 0, 0, 1.f, nullptr);
    // GRU recurrence (16 clusters of 8, DSMEM push + mbarrier)
    gru_kernel<<<128, 384>>>(w_hh_f, w_hh_b, b_hh_f, b_hh_b, masks,
                             out + (size_t)NB * NS * ND);
    // LN1
    ln_kernel<<<M, 128>>>(gru, nullptr, ln1_g, ln1_b, ln1);
    // Q/K/V projections with head scatter — tf32
    gemm_tf32<<<dim3(4, 128, 1), 256>>>(ln1, wq, bq, q,  M, ND, ND, 0, 0, 0, 1, 1.f, nullptr);
    gemm_tf32<<<dim3(4, 128, 1), 256>>>(ln1, wk, bk, k,  M, ND, ND, 0, 0, 0, 1, 1.f, nullptr);
    gemm_tf32<<<dim3(4, 128, 1), 256>>>(ln1, wv, bv, vt, M, ND, ND, 0, 0, 0, 2, 1.f, nullptr);
    // scores = q @ k^T / 8   (z = b*8+h) — tf32
    gemm_tf32<<<dim3(4, 4, 256), 256>>>(q, k, nullptr, sc, NS, NS, NDK,
                                        (long)NS * NDK, (long)NS * NDK, (long)NS * NS,
                                        3, 0.125f, nullptr);
    // masked prefix softmax (in place)
    softmax_kernel<<<dim3(NS, 256), 128>>>(sc, lengths);
    // attn = p @ v  -> concat layout — tf32
    gemm_tf32<<<dim3(1, 4, 256), 256>>>(sc, vt, nullptr, cc, NS, NDK, NS,
                                        (long)NS * NS, (long)NS * NDK, 0,
                                        4, 1.f, nullptr);
    // out projection + row mask — tf32
    gemm_tf32<<<dim3(4, 128, 1), 256>>>(cc, wo, bo, oo, M, ND, ND, 0, 0, 0, 5, 1.f, masks);
    // residual + LN2 -> final outputs
    ln_kernel<<<M, 128>>>(ln1, oo, ln2_g, ln2_b, out);
}

// round 11
// speedup vs baseline: 1.7468x; 1.7468x over previous
#include <cuda_runtime.h>
#include <cstdint>
#include <cstddef>

#define NB   32
#define NS   512
#define ND   512
#define NH2  256
#define NG3  768
#define NDK  64

// ------------------------- scratch (device globals) -------------------------
__device__ float g_xg[(size_t)2 * NB * NS * NG3];   // gate preactivations, per dir
__device__ float g_gru[(size_t)NB * NS * ND];       // concat GRU outputs
__device__ float g_ln1[(size_t)NB * NS * ND];       // ln1("outputs")
__device__ float g_q [(size_t)NB * 8 * NS * NDK];   // (b,h,s,d)
__device__ float g_k [(size_t)NB * 8 * NS * NDK];   // (b,h,s,d)
__device__ float g_vt[(size_t)NB * 8 * NDK * NS];   // (b,h,d,s)
__device__ float g_sc[(size_t)NB * 8 * NS * NS];    // scores -> p
__device__ float g_cc[(size_t)NB * NS * ND];        // attn concat
__device__ float g_o [(size_t)NB * NS * ND];        // out projection
__device__ float g_hx[16 * 2048];                   // h exchange (16 groups x 2 bufs x 1024)
__device__ unsigned g_flag[16 * 8 * 4 * 32];        // per (group,rank,warp) flag, 1 per 128B line

// ------------------------- f32x2 helpers -------------------------
__device__ __forceinline__ unsigned long long fma2(unsigned long long a,
                                                   unsigned long long b,
                                                   unsigned long long c) {
    unsigned long long d;
    asm("fma.rn.f32x2 %0, %1, %2, %3;" : "=l"(d) : "l"(a), "l"(b), "l"(c));
    return d;
}
__device__ __forceinline__ unsigned long long pack2(float x, float y) {
    unsigned long long d;
    asm("mov.b64 %0, {%1, %2};" : "=l"(d) : "f"(x), "f"(y));
    return d;
}
__device__ __forceinline__ void unpack2(unsigned long long v, float& x, float& y) {
    asm("mov.b64 {%0, %1}, %2;" : "=f"(x), "=f"(y) : "l"(v));
}
__device__ __forceinline__ float tf32r(float f) {
    unsigned u;
    asm("cvt.rna.tf32.f32 %0, %1;" : "=r"(u) : "f"(f));
    return __uint_as_float(u);
}

// ------------------------- epilogue store -------------------------
// modes:
// 0: +bias              1: +bias, scatter (b,h,s,d)   2: +bias, scatter (b,h,d,s)
// 3: *scale             4: scatter concat (b,s,h*64+d) 5: +bias, *rowmask(masks)
__device__ __forceinline__ void store_elem(float* C, const float* bias,
                                           const int* masks, int mode, float scale,
                                           int z, int N, int mrow, int nc, float v) {
    if (nc >= N) return;
    if (mode == 0) {
        C[(long)mrow * N + nc] = v + bias[nc];
    } else if (mode == 1) {
        int b = mrow >> 9, s = mrow & 511, h = nc >> 6, d = nc & 63;
        C[(((long)(b * 8 + h) * NS + s)) * NDK + d] = v + bias[nc];
    } else if (mode == 2) {
        int b = mrow >> 9, s = mrow & 511, h = nc >> 6, d = nc & 63;
        C[((long)(b * 8 + h) * NDK + d) * NS + s] = v + bias[nc];
    } else if (mode == 3) {
        C[(long)mrow * N + nc] = v * scale;
    } else if (mode == 4) {
        int b = z >> 3, h = z & 7;
        C[((long)(b * NS + mrow)) * ND + h * NDK + nc] = v;
    } else {
        C[(long)mrow * N + nc] = masks[mrow] ? (v + bias[nc]) : 0.f;
    }
}

// ------------------------- tf32 tensor-core TN GEMM -------------------------
// C = epi(A[M,K] @ W[N,K]^T) via mma.sync.m16n8k8 tf32.
// 128x128x16 tile, 256 thr = 8 warps (2x4), each warp 64x32.
__global__ void __launch_bounds__(256) gemm_tf32(
    const float* __restrict__ A, const float* __restrict__ W,
    const float* __restrict__ bias, float* __restrict__ C,
    int M, int N, int K, long sA, long sW, long sC,
    int mode, float scale, const int* __restrict__ masks)
{
    __shared__ float As[128][20];   // [m][k], pad 20 -> conflict-free frag loads
    __shared__ float Ws[128][20];   // [n][k]

    const int z = blockIdx.z;
    A += (long)z * sA;
    W += (long)z * sW;
    if (mode == 3) C += (long)z * sC;

    const int m0 = blockIdx.y * 128, n0 = blockIdx.x * 128;
    const int tid  = threadIdx.x;
    const int warp = tid >> 5, lane = tid & 31;
    const int wm = warp >> 2, wn = warp & 3;   // warp grid 2 x 4
    const int g  = lane >> 2, tg = lane & 3;   // mma group / thread-in-group

    const int lm = tid >> 2, lkq = tid & 3;
    const float* Aip = A + (long)(m0 + lm) * K + lkq * 4;
    const float* Wip = W + (long)(n0 + lm) * K + lkq * 4;
    const bool w0ok = (n0 + lm) < N;
    const bool w1ok = (n0 + lm + 64) < N;
    const float4 z4 = make_float4(0.f, 0.f, 0.f, 0.f);

    float acc[4][4][4];
#pragma unroll
    for (int mt = 0; mt < 4; mt++)
#pragma unroll
        for (int nt = 0; nt < 4; nt++)
#pragma unroll
            for (int c = 0; c < 4; c++) acc[mt][nt][c] = 0.f;

    float4 a0v = *(const float4*)Aip;
    float4 a1v = *(const float4*)(Aip + (long)64 * K);
    float4 w0v = w0ok ? *(const float4*)Wip : z4;
    float4 w1v = w1ok ? *(const float4*)(Wip + (long)64 * K) : z4;

    for (int k0 = 0; k0 < K; k0 += 16) {
        __syncthreads();
        {
            float* pa0 = &As[lm][lkq * 4];
            pa0[0] = tf32r(a0v.x); pa0[1] = tf32r(a0v.y);
            pa0[2] = tf32r(a0v.z); pa0[3] = tf32r(a0v.w);
            float* pa1 = &As[lm + 64][lkq * 4];
            pa1[0] = tf32r(a1v.x); pa1[1] = tf32r(a1v.y);
            pa1[2] = tf32r(a1v.z); pa1[3] = tf32r(a1v.w);
            float* pw0 = &Ws[lm][lkq * 4];
            pw0[0] = tf32r(w0v.x); pw0[1] = tf32r(w0v.y);
            pw0[2] = tf32r(w0v.z); pw0[3] = tf32r(w0v.w);
            float* pw1 = &Ws[lm + 64][lkq * 4];
            pw1[0] = tf32r(w1v.x); pw1[1] = tf32r(w1v.y);
            pw1[2] = tf32r(w1v.z); pw1[3] = tf32r(w1v.w);
        }
        __syncthreads();
        if (k0 + 16 < K) {
            a0v = *(const float4*)(Aip + k0 + 16);
            a1v = *(const float4*)(Aip + (long)64 * K + k0 + 16);
            w0v = w0ok ? *(const float4*)(Wip + k0 + 16) : z4;
            w1v = w1ok ? *(const float4*)(Wip + (long)64 * K + k0 + 16) : z4;
        }
#pragma unroll
        for (int kb = 0; kb < 2; kb++) {
            const int kk = kb * 8 + tg;
            unsigned a[4][4], b[4][2];
#pragma unroll
            for (int mt = 0; mt < 4; mt++) {
                const int rm = wm * 64 + mt * 16 + g;
                a[mt][0] = __float_as_uint(As[rm][kk]);
                a[mt][1] = __float_as_uint(As[rm + 8][kk]);
                a[mt][2] = __float_as_uint(As[rm][kk + 4]);
                a[mt][3] = __float_as_uint(As[rm + 8][kk + 4]);
            }
#pragma unroll
            for (int nt = 0; nt < 4; nt++) {
                const int rn = wn * 32 + nt * 8 + g;
                b[nt][0] = __float_as_uint(Ws[rn][kk]);
                b[nt][1] = __float_as_uint(Ws[rn][kk + 4]);
            }
#pragma unroll
            for (int mt = 0; mt < 4; mt++)
#pragma unroll
                for (int nt = 0; nt < 4; nt++) {
                    asm volatile(
                        "mma.sync.aligned.m16n8k8.row.col.f32.tf32.tf32.f32 "
                        "{%0,%1,%2,%3}, {%4,%5,%6,%7}, {%8,%9}, {%0,%1,%2,%3};"
                        : "+f"(acc[mt][nt][0]), "+f"(acc[mt][nt][1]),
                          "+f"(acc[mt][nt][2]), "+f"(acc[mt][nt][3])
                        : "r"(a[mt][0]), "r"(a[mt][1]), "r"(a[mt][2]), "r"(a[mt][3]),
                          "r"(b[nt][0]), "r"(b[nt][1]));
                }
        }
    }

#pragma unroll
    for (int mt = 0; mt < 4; mt++) {
#pragma unroll
        for (int nt = 0; nt < 4; nt++) {
            const int row0 = m0 + wm * 64 + mt * 16 + g;
            const int col0 = n0 + wn * 32 + nt * 8 + 2 * tg;
            store_elem(C, bias, masks, mode, scale, z, N, row0,     col0,     acc[mt][nt][0]);
            store_elem(C, bias, masks, mode, scale, z, N, row0,     col0 + 1, acc[mt][nt][1]);
            store_elem(C, bias, masks, mode, scale, z, N, row0 + 8, col0,     acc[mt][nt][2]);
            store_elem(C, bias, masks, mode, scale, z, N, row0 + 8, col0 + 1, acc[mt][nt][3]);
        }
    }
}

// ------------------------- flag reset -------------------------
__global__ void reset_kernel() {
    g_flag[blockIdx.x * 256 + threadIdx.x] = 0u;
}

// ------------------------- persistent GRU (flag mailbox, warp-grain sync) ---
// 128 blocks = dir(2) x batchgroup(8 of 4 batches) x jchunk(8 of 32 j).
// 384 threads = rg(48, 2 gate-rows) x ks(8, 32-k slice); weights in registers.
// h exchange via L2 (st.cg, plain float layout, double-buffered).
// Release: per producer WARP (one batch, 32 h): st.cg x32 -> __syncwarp ->
//          lane0: __threadfence + flag store (32 flags/group, own 128B lines).
// Acquire: per consumer THREAD: acquire-poll the one flag covering its 16B
//          chunk, then ld.cg.v4 the data directly. No detect->broadcast hop.
// smem h single-buffered, XOR-swizzled (chunk (ks<<3)|(i^ks)) -> conflict-free.
__global__ void __launch_bounds__(384, 1) gru_kernel(
    const float* __restrict__ whf, const float* __restrict__ whb,
    const float* __restrict__ bhf, const float* __restrict__ bhb,
    const int* __restrict__ masks, float* __restrict__ hid_out)
{
    __shared__ float sh_h[1024];     // [b][swizzled k] h for 4 batches
    __shared__ float sh_gate[384];   // [row][b]

    const int bid = blockIdx.x;
    const int dir = bid >> 6;
    const int rem = bid & 63;
    const int bg  = rem >> 3;
    const int jc  = rem & 7;
    const int grp = dir * 8 + bg;
    const int tid = threadIdx.x;
    const int rg  = tid >> 3;        // 0..47 (gate-row pair)
    const int ks  = tid & 7;         // k eighth (32 values)
    const int row0 = rg * 2, row1 = rg * 2 + 1;
    const int G0 = (row0 >> 5) * 256 + jc * 32 + (row0 & 31);
    const int G1 = (row1 >> 5) * 256 + jc * 32 + (row1 & 31);

    const float* wh = dir ? whb : whf;
    const float* bh = dir ? bhb : bhf;
    const float bh0 = bh[G0], bh1 = bh[G1];

    unsigned long long wp0[16], wp1[16];
    {
        const float* w0s = wh + (long)G0 * NH2 + ks * 32;
        const float* w1s = wh + (long)G1 * NH2 + ks * 32;
#pragma unroll
        for (int i = 0; i < 16; i++) {
            wp0[i] = pack2(w0s[2 * i], w0s[2 * i + 1]);
            wp1[i] = pack2(w1s[2 * i], w1s[2 * i + 1]);
        }
    }

    const int ju = tid & 31, bu = tid >> 5;   // updater role (tid < 128)
    const int jglob = jc * 32 + ju;
    const int bglob = bg * 4 + bu;
    const float* xgp = g_xg + ((size_t)dir * NB + bglob) * NS * NG3;
    float* hxg = g_hx + grp * 2048;           // 2 bufs x 1024 floats
    // producer flag: (group, rank=jc, warp=bu), one per 128B line
    unsigned* myflag = &g_flag[(((grp * 8) + jc) * 4 + bu) * 32];

    // consumer precompute (tid < 256): floats 4*tid..4*tid+3
    const int c4  = tid * 4;
    const int cbb = c4 >> 8;                  // batch (producer warp)
    const int jj  = c4 & 255;                 // j index
    const int jcc = jj >> 5;                  // producer rank
    const unsigned* flp = &g_flag[(((grp * 8) + jcc) * 4 + cbb) * 32];
    const int cc0 = jj >> 2;                  // logical chunk within batch
    const int csw = ((cc0 >> 3) << 3) | ((cc0 & 7) ^ (cc0 >> 3));
    float* shdst = &sh_h[cbb * 256 + csw * 4];

    for (int i = tid; i < 1024; i += 384) sh_h[i] = 0.f;
    float hreg = 0.f;
    __syncthreads();

    for (int t = 0; t < NS; t++) {
        const int s = dir ? (NS - 1 - t) : t;
        float xr = 0.f, xz = 0.f, xn = 0.f;
        int mk = 0;
        if (tid < 128) {  // prefetch x-gates + mask (independent of h)
            const float* xrow = xgp + (size_t)s * NG3;
            xr = __ldg(xrow + jglob);
            xz = __ldg(xrow + NH2 + jglob);
            xn = __ldg(xrow + 2 * NH2 + jglob);
            mk = __ldg(masks + bglob * NS + s);
        }
        if (t > 0) {
            if (tid < 256) {
                const unsigned tgt = (unsigned)t;
                unsigned v;
                do {
                    asm volatile("ld.global.acquire.gpu.u32 %0, [%1];"
                                 : "=r"(v) : "l"(flp) : "memory");
                } while (v < tgt);
                const float* src = hxg + ((t - 1) & 1) * 1024 + tid * 4;
                float4 hv4;
                asm volatile("ld.global.cg.v4.f32 {%0,%1,%2,%3}, [%4];"
                             : "=f"(hv4.x), "=f"(hv4.y), "=f"(hv4.z), "=f"(hv4.w)
                             : "l"(src) : "memory");
                *(float4*)shdst = hv4;
            }
            __syncthreads();
        }
        // gate dot products: 2 gate-rows x 4 batches, k slice ks*32..+31
        unsigned long long a0[4] = {0ull, 0ull, 0ull, 0ull};
        unsigned long long a1[4] = {0ull, 0ull, 0ull, 0ull};
#pragma unroll
        for (int i = 0; i < 8; i++) {
            const int coff = (((ks << 3) | (i ^ ks)) << 2);
#pragma unroll
            for (int b = 0; b < 4; b++) {
                ulonglong2 hv = *(const ulonglong2*)(sh_h + b * 256 + coff);
                a0[b] = fma2(wp0[2 * i],     hv.x, a0[b]);
                a0[b] = fma2(wp0[2 * i + 1], hv.y, a0[b]);
                a1[b] = fma2(wp1[2 * i],     hv.x, a1[b]);
                a1[b] = fma2(wp1[2 * i + 1], hv.y, a1[b]);
            }
        }
        float v0[4], v1[4];
#pragma unroll
        for (int b = 0; b < 4; b++) {
            float lo, hi;
            unpack2(a0[b], lo, hi); v0[b] = lo + hi;
            unpack2(a1[b], lo, hi); v1[b] = lo + hi;
        }
        // butterfly-reduce over the 8 ks lanes
#pragma unroll
        for (int off = 1; off < 8; off <<= 1) {
#pragma unroll
            for (int b = 0; b < 4; b++) {
                v0[b] += __shfl_xor_sync(~0u, v0[b], off);
                v1[b] += __shfl_xor_sync(~0u, v1[b], off);
            }
        }
        if (ks == 0) {
            float4 f0 = make_float4(v0[0] + bh0, v0[1] + bh0, v0[2] + bh0, v0[3] + bh0);
            float4 f1 = make_float4(v1[0] + bh1, v1[1] + bh1, v1[2] + bh1, v1[3] + bh1);
            *(float4*)&sh_gate[rg * 8]     = f0;
            *(float4*)&sh_gate[rg * 8 + 4] = f1;
        }
        __syncthreads();   // gates ready; also: ALL reads of sh_h done
        if (tid < 128) {
            const float hgr = sh_gate[ju * 4 + bu];
            const float hgz = sh_gate[(32 + ju) * 4 + bu];
            const float hgn = sh_gate[(64 + ju) * 4 + bu];
            const float rr = 1.f / (1.f + __expf(-(xr + hgr)));
            const float zz = 1.f / (1.f + __expf(-(xz + hgz)));
            const float na = xn + rr * hgn;
            const float nn = 2.f / (1.f + __expf(-2.f * na)) - 1.f;  // tanh
            const float hnew = (1.f - zz) * nn + zz * hreg;
            hreg = mk ? hnew : hreg;
            g_gru[((size_t)bglob * NS + s) * ND + dir * NH2 + jglob] = mk ? hreg : 0.f;
            if (t == NS - 1) {
                hid_out[bglob * ND + dir * NH2 + jglob] = hreg;
            } else {
                __stcg(hxg + (t & 1) * 1024 + bu * 256 + jglob, hreg);
                __syncwarp();               // warp's 32 h stores complete
                if (ju == 0) {
                    __threadfence();        // order them before the flag
                    unsigned nv = (unsigned)(t + 1);
                    asm volatile("st.global.cg.u32 [%0], %1;"
                                 :: "l"(myflag), "r"(nv) : "memory");
                }
            }
        }
    }
}

// ------------------------- layernorm (optionally fused residual) -------------------------
__global__ void __launch_bounds__(128) ln_kernel(
    const float* __restrict__ x, const float* __restrict__ y,
    const float* __restrict__ gam, const float* __restrict__ bet,
    float* __restrict__ out)
{
    __shared__ float red[8];
    const int row = blockIdx.x;
    const int tid = threadIdx.x;
    float4 v = *(const float4*)(x + (size_t)row * ND + tid * 4);
    if (y) {
        float4 w = *(const float4*)(y + (size_t)row * ND + tid * 4);
        v.x += w.x; v.y += w.y; v.z += w.z; v.w += w.w;
    }
    float s1 = v.x + v.y + v.z + v.w;
    float s2 = v.x * v.x + v.y * v.y + v.z * v.z + v.w * v.w;
#pragma unroll
    for (int o = 16; o; o >>= 1) {
        s1 += __shfl_xor_sync(~0u, s1, o);
        s2 += __shfl_xor_sync(~0u, s2, o);
    }
    const int wid = tid >> 5;
    if ((tid & 31) == 0) { red[wid] = s1; red[wid + 4] = s2; }
    __syncthreads();
    s1 = red[0] + red[1] + red[2] + red[3];
    s2 = red[4] + red[5] + red[6] + red[7];
    const float mu = s1 * (1.f / ND);
    const float var = s2 * (1.f / ND) - mu * mu;
    const float rs = rsqrtf(var + 1e-5f);
    const float4 gv = *(const float4*)(gam + tid * 4);
    const float4 bv = *(const float4*)(bet + tid * 4);
    float4 o4;
    o4.x = (v.x - mu) * rs * gv.x + bv.x;
    o4.y = (v.y - mu) * rs * gv.y + bv.y;
    o4.z = (v.z - mu) * rs * gv.z + bv.z;
    o4.w = (v.w - mu) * rs * gv.w + bv.w;
    *(float4*)(out + (size_t)row * ND + tid * 4) = o4;
}

// ------------------------- masked prefix softmax -------------------------
__global__ void __launch_bounds__(128) softmax_kernel(
    float* __restrict__ P, const int* __restrict__ lengths)
{
    __shared__ float red[4];
    const int q = blockIdx.x, z = blockIdx.y;
    const int len = __ldg(lengths + (z >> 3));
    float* row = P + ((size_t)z * NS + q) * NS;
    const int tid = threadIdx.x;
    const int c0 = tid * 4;
    if (q >= len) {
        *(float4*)(row + c0) = make_float4(0.f, 0.f, 0.f, 0.f);
        return;
    }
    float4 v = *(const float4*)(row + c0);
    const bool b0 = c0 < len, b1 = c0 + 1 < len, b2 = c0 + 2 < len, b3 = c0 + 3 < len;
    float m = -1e30f;
    if (b0) m = fmaxf(m, v.x);
    if (b1) m = fmaxf(m, v.y);
    if (b2) m = fmaxf(m, v.z);
    if (b3) m = fmaxf(m, v.w);
#pragma unroll
    for (int o = 16; o; o >>= 1) m = fmaxf(m, __shfl_xor_sync(~0u, m, o));
    const int wid = tid >> 5;
    if ((tid & 31) == 0) red[wid] = m;
    __syncthreads();
    m = fmaxf(fmaxf(red[0], red[1]), fmaxf(red[2], red[3]));
    __syncthreads();
    float4 e;
    e.x = b0 ? __expf(v.x - m) : 0.f;
    e.y = b1 ? __expf(v.y - m) : 0.f;
    e.z = b2 ? __expf(v.z - m) : 0.f;
    e.w = b3 ? __expf(v.w - m) : 0.f;
    float s = e.x + e.y + e.z + e.w;
#pragma unroll
    for (int o = 16; o; o >>= 1) s += __shfl_xor_sync(~0u, s, o);
    if ((tid & 31) == 0) red[wid] = s;
    __syncthreads();
    s = red[0] + red[1] + red[2] + red[3];
    const float inv = 1.f / s;
    e.x *= inv; e.y *= inv; e.z *= inv; e.w *= inv;
    *(float4*)(row + c0) = e;
}

// ------------------------- launch -------------------------
extern "C" void kernel_launch(void* const* d_in, const int* in_sizes, int n_in,
                              void* d_out, int out_size)
{
    const float* splits = (const float*)d_in[0];
    const float* w_ih_f = (const float*)d_in[1];
    const float* w_hh_f = (const float*)d_in[2];
    const float* b_ih_f = (const float*)d_in[3];
    const float* b_hh_f = (const float*)d_in[4];
    const float* w_ih_b = (const float*)d_in[5];
    const float* w_hh_b = (const float*)d_in[6];
    const float* b_ih_b = (const float*)d_in[7];
    const float* b_hh_b = (const float*)d_in[8];
    const float* ln1_g  = (const float*)d_in[9];
    const float* ln1_b  = (const float*)d_in[10];
    const float* wq = (const float*)d_in[11];
    const float* bq = (const float*)d_in[12];
    const float* wk = (const float*)d_in[13];
    const float* bk = (const float*)d_in[14];
    const float* wv = (const float*)d_in[15];
    const float* bv = (const float*)d_in[16];
    const float* wo = (const float*)d_in[17];
    const float* bo = (const float*)d_in[18];
    const float* ln2_g = (const float*)d_in[19];
    const float* ln2_b = (const float*)d_in[20];
    const int* lengths = (const int*)d_in[21];
    const int* masks   = (const int*)d_in[22];
    float* out = (float*)d_out;

    float *xg, *gru, *ln1, *q, *k, *vt, *sc, *cc, *oo;
    cudaGetSymbolAddress((void**)&xg,  g_xg);
    cudaGetSymbolAddress((void**)&gru, g_gru);
    cudaGetSymbolAddress((void**)&ln1, g_ln1);
    cudaGetSymbolAddress((void**)&q,   g_q);
    cudaGetSymbolAddress((void**)&k,   g_k);
    cudaGetSymbolAddress((void**)&vt,  g_vt);
    cudaGetSymbolAddress((void**)&sc,  g_sc);
    cudaGetSymbolAddress((void**)&cc,  g_cc);
    cudaGetSymbolAddress((void**)&oo,  g_o);

    const int M = NB * NS;  // 16384

    // GRU input projections (both dirs) — tf32 tensor cores
    gemm_tf32<<<dim3(6, 128, 1), 256>>>(splits, w_ih_f, b_ih_f, xg,
                                        M, NG3, ND, 0, 0, 0, 0, 1.f, nullptr);
    gemm_tf32<<<dim3(6, 128, 1), 256>>>(splits, w_ih_b, b_ih_b, xg + (size_t)M * NG3,
                                        M, NG3, ND, 0, 0, 0, 0, 1.f, nullptr);
    // GRU recurrence (persistent, per-(rank,warp) flag sync through L2)
    reset_kernel<<<64, 256>>>();
    gru_kernel<<<128, 384>>>(w_hh_f, w_hh_b, b_hh_f, b_hh_b, masks,
                             out + (size_t)NB * NS * ND);
    // LN1
    ln_kernel<<<M, 128>>>(gru, nullptr, ln1_g, ln1_b, ln1);
    // Q/K/V projections with head scatter — tf32
    gemm_tf32<<<dim3(4, 128, 1), 256>>>(ln1, wq, bq, q,  M, ND, ND, 0, 0, 0, 1, 1.f, nullptr);
    gemm_tf32<<<dim3(4, 128, 1), 256>>>(ln1, wk, bk, k,  M, ND, ND, 0, 0, 0, 1, 1.f, nullptr);
    gemm_tf32<<<dim3(4, 128, 1), 256>>>(ln1, wv, bv, vt, M, ND, ND, 0, 0, 0, 2, 1.f, nullptr);
    // scores = q @ k^T / 8   (z = b*8+h) — tf32
    gemm_tf32<<<dim3(4, 4, 256), 256>>>(q, k, nullptr, sc, NS, NS, NDK,
                                        (long)NS * NDK, (long)NS * NDK, (long)NS * NS,
                                        3, 0.125f, nullptr);
    // masked prefix softmax (in place)
    softmax_kernel<<<dim3(NS, 256), 128>>>(sc, lengths);
    // attn = p @ v  -> concat layout — tf32
    gemm_tf32<<<dim3(1, 4, 256), 256>>>(sc, vt, nullptr, cc, NS, NDK, NS,
                                        (long)NS * NS, (long)NS * NDK, 0,
                                        4, 1.f, nullptr);
    // out projection + row mask — tf32
    gemm_tf32<<<dim3(4, 128, 1), 256>>>(cc, wo, bo, oo, M, ND, ND, 0, 0, 0, 5, 1.f, masks);
    // residual + LN2 -> final outputs
    ln_kernel<<<M, 128>>>(ln1, oo, ln2_g, ln2_b, out);
}

// round 12
// speedup vs baseline: 2.0660x; 1.1828x over previous
#include <cuda_runtime.h>
#include <cstdint>
#include <cstddef>

#define NB   32
#define NS   512
#define ND   512
#define NH2  256
#define NG3  768
#define NDK  64

// ------------------------- scratch (device globals) -------------------------
__device__ float g_xg[(size_t)2 * NB * NS * NG3];   // gate preactivations, per dir
__device__ float g_gru[(size_t)NB * NS * ND];       // concat GRU outputs
__device__ float g_ln1[(size_t)NB * NS * ND];       // ln1("outputs")
__device__ float g_q [(size_t)NB * 8 * NS * NDK];   // (b,h,s,d)
__device__ float g_k [(size_t)NB * 8 * NS * NDK];   // (b,h,s,d)
__device__ float g_vt[(size_t)NB * 8 * NDK * NS];   // (b,h,d,s)
__device__ float g_cc[(size_t)NB * NS * ND];        // attn concat
__device__ float g_o [(size_t)NB * NS * ND];        // out projection
__device__ float g_hx[16 * 2048];                   // h exchange (16 groups x 2 bufs x 1024)
__device__ unsigned g_flag[16 * 8 * 32];            // per (group,rank) step flag, 1 per 128B line

// ------------------------- f32x2 helpers -------------------------
__device__ __forceinline__ unsigned long long fma2(unsigned long long a,
                                                   unsigned long long b,
                                                   unsigned long long c) {
    unsigned long long d;
    asm("fma.rn.f32x2 %0, %1, %2, %3;" : "=l"(d) : "l"(a), "l"(b), "l"(c));
    return d;
}
__device__ __forceinline__ unsigned long long pack2(float x, float y) {
    unsigned long long d;
    asm("mov.b64 %0, {%1, %2};" : "=l"(d) : "f"(x), "f"(y));
    return d;
}
__device__ __forceinline__ void unpack2(unsigned long long v, float& x, float& y) {
    asm("mov.b64 {%0, %1}, %2;" : "=f"(x), "=f"(y) : "l"(v));
}
__device__ __forceinline__ float tf32r(float f) {
    unsigned u;
    asm("cvt.rna.tf32.f32 %0, %1;" : "=r"(u) : "f"(f));
    return __uint_as_float(u);
}
__device__ __forceinline__ void mma_tf32(float* acc, const unsigned* a, const unsigned* b) {
    asm volatile(
        "mma.sync.aligned.m16n8k8.row.col.f32.tf32.tf32.f32 "
        "{%0,%1,%2,%3}, {%4,%5,%6,%7}, {%8,%9}, {%0,%1,%2,%3};"
        : "+f"(acc[0]), "+f"(acc[1]), "+f"(acc[2]), "+f"(acc[3])
        : "r"(a[0]), "r"(a[1]), "r"(a[2]), "r"(a[3]),
          "r"(b[0]), "r"(b[1]));
}

// ------------------------- epilogue store -------------------------
// 0: +bias   1: +bias, scatter (b,h,s,d)   2: +bias, scatter (b,h,d,s)
// 5: +bias, *rowmask(masks)
__device__ __forceinline__ void store_elem(float* C, const float* bias,
                                           const int* masks, int mode, float scale,
                                           int z, int N, int mrow, int nc, float v) {
    if (nc >= N) return;
    if (mode == 0) {
        C[(long)mrow * N + nc] = v + bias[nc];
    } else if (mode == 1) {
        int b = mrow >> 9, s = mrow & 511, h = nc >> 6, d = nc & 63;
        C[(((long)(b * 8 + h) * NS + s)) * NDK + d] = v + bias[nc];
    } else if (mode == 2) {
        int b = mrow >> 9, s = mrow & 511, h = nc >> 6, d = nc & 63;
        C[((long)(b * 8 + h) * NDK + d) * NS + s] = v + bias[nc];
    } else {
        C[(long)mrow * N + nc] = masks[mrow] ? (v + bias[nc]) : 0.f;
    }
}

// ------------------------- tf32 tensor-core TN GEMM -------------------------
__global__ void __launch_bounds__(256) gemm_tf32(
    const float* __restrict__ A, const float* __restrict__ W,
    const float* __restrict__ bias, float* __restrict__ C,
    int M, int N, int K, int mode, float scale, const int* __restrict__ masks)
{
    __shared__ float As[128][20];
    __shared__ float Ws[128][20];

    const int m0 = blockIdx.y * 128, n0 = blockIdx.x * 128;
    const int tid  = threadIdx.x;
    const int warp = tid >> 5, lane = tid & 31;
    const int wm = warp >> 2, wn = warp & 3;
    const int g  = lane >> 2, tg = lane & 3;

    const int lm = tid >> 2, lkq = tid & 3;
    const float* Aip = A + (long)(m0 + lm) * K + lkq * 4;
    const float* Wip = W + (long)(n0 + lm) * K + lkq * 4;
    const bool w0ok = (n0 + lm) < N;
    const bool w1ok = (n0 + lm + 64) < N;
    const float4 z4 = make_float4(0.f, 0.f, 0.f, 0.f);

    float acc[4][4][4];
#pragma unroll
    for (int mt = 0; mt < 4; mt++)
#pragma unroll
        for (int nt = 0; nt < 4; nt++)
#pragma unroll
            for (int c = 0; c < 4; c++) acc[mt][nt][c] = 0.f;

    float4 a0v = *(const float4*)Aip;
    float4 a1v = *(const float4*)(Aip + (long)64 * K);
    float4 w0v = w0ok ? *(const float4*)Wip : z4;
    float4 w1v = w1ok ? *(const float4*)(Wip + (long)64 * K) : z4;

    for (int k0 = 0; k0 < K; k0 += 16) {
        __syncthreads();
        {
            float* pa0 = &As[lm][lkq * 4];
            pa0[0] = tf32r(a0v.x); pa0[1] = tf32r(a0v.y);
            pa0[2] = tf32r(a0v.z); pa0[3] = tf32r(a0v.w);
            float* pa1 = &As[lm + 64][lkq * 4];
            pa1[0] = tf32r(a1v.x); pa1[1] = tf32r(a1v.y);
            pa1[2] = tf32r(a1v.z); pa1[3] = tf32r(a1v.w);
            float* pw0 = &Ws[lm][lkq * 4];
            pw0[0] = tf32r(w0v.x); pw0[1] = tf32r(w0v.y);
            pw0[2] = tf32r(w0v.z); pw0[3] = tf32r(w0v.w);
            float* pw1 = &Ws[lm + 64][lkq * 4];
            pw1[0] = tf32r(w1v.x); pw1[1] = tf32r(w1v.y);
            pw1[2] = tf32r(w1v.z); pw1[3] = tf32r(w1v.w);
        }
        __syncthreads();
        if (k0 + 16 < K) {
            a0v = *(const float4*)(Aip + k0 + 16);
            a1v = *(const float4*)(Aip + (long)64 * K + k0 + 16);
            w0v = w0ok ? *(const float4*)(Wip + k0 + 16) : z4;
            w1v = w1ok ? *(const float4*)(Wip + (long)64 * K + k0 + 16) : z4;
        }
#pragma unroll
        for (int kb = 0; kb < 2; kb++) {
            const int kk = kb * 8 + tg;
            unsigned a[4][4], b[4][2];
#pragma unroll
            for (int mt = 0; mt < 4; mt++) {
                const int rm = wm * 64 + mt * 16 + g;
                a[mt][0] = __float_as_uint(As[rm][kk]);
                a[mt][1] = __float_as_uint(As[rm + 8][kk]);
                a[mt][2] = __float_as_uint(As[rm][kk + 4]);
                a[mt][3] = __float_as_uint(As[rm + 8][kk + 4]);
            }
#pragma unroll
            for (int nt = 0; nt < 4; nt++) {
                const int rn = wn * 32 + nt * 8 + g;
                b[nt][0] = __float_as_uint(Ws[rn][kk]);
                b[nt][1] = __float_as_uint(Ws[rn][kk + 4]);
            }
#pragma unroll
            for (int mt = 0; mt < 4; mt++)
#pragma unroll
                for (int nt = 0; nt < 4; nt++)
                    mma_tf32(acc[mt][nt], a[mt], b[nt]);
        }
    }

#pragma unroll
    for (int mt = 0; mt < 4; mt++) {
#pragma unroll
        for (int nt = 0; nt < 4; nt++) {
            const int row0 = m0 + wm * 64 + mt * 16 + g;
            const int col0 = n0 + wn * 32 + nt * 8 + 2 * tg;
            store_elem(C, bias, masks, mode, scale, 0, N, row0,     col0,     acc[mt][nt][0]);
            store_elem(C, bias, masks, mode, scale, 0, N, row0,     col0 + 1, acc[mt][nt][1]);
            store_elem(C, bias, masks, mode, scale, 0, N, row0 + 8, col0,     acc[mt][nt][2]);
            store_elem(C, bias, masks, mode, scale, 0, N, row0 + 8, col0 + 1, acc[mt][nt][3]);
        }
    }
}

// ------------------------- fused attention (scores+softmax+PV) --------------
// grid (qt=4, z=256); 256 thr = warps wm(4) x wn(2). q-tile 128, k-chunks 64.
// Online softmax; prefix mask; length-aware chunk skip; out rows q>=len -> 0.
#define ATTN_SMEM_FLOATS (128*68 + 64*68 + 64*68 + 256 + 256)
__global__ void __launch_bounds__(256) attn_kernel(
    const float* __restrict__ Q, const float* __restrict__ K,
    const float* __restrict__ VT, float* __restrict__ CC,
    const int* __restrict__ lengths)
{
    extern __shared__ float sm[];
    float* Ps   = sm;                    // [128][68]; Q staging then P
    float* Ks   = sm + 128 * 68;         // [64][68]
    float* Vs   = Ks + 64 * 68;          // [64][68]
    float* smax = Vs + 64 * 68;          // [2][128]
    float* ssum = smax + 256;            // [2][128]

    const int qt = blockIdx.x, z = blockIdx.y;
    const int b = z >> 3, h = z & 7;
    const int q0 = qt * 128;
    const int len = __ldg(lengths + b);
    const int tid = threadIdx.x;
    const int warp = tid >> 5, lane = tid & 31;
    const int wm = warp >> 1, wn = warp & 1;
    const int g = lane >> 2, tg = lane & 3;

    // stage Q tile (tf32) into Ps
    const float* Qb = Q + ((size_t)z * NS + q0) * NDK;
#pragma unroll
    for (int i = 0; i < 8; i++) {
        const int idx = tid * 32 + i * 4;
        const int r = idx >> 6, c = idx & 63;
        float4 v = *(const float4*)(Qb + r * 64 + c);
        float* d = &Ps[r * 68 + c];
        d[0] = tf32r(v.x); d[1] = tf32r(v.y); d[2] = tf32r(v.z); d[3] = tf32r(v.w);
    }
    __syncthreads();

    // Q fragments -> registers
    unsigned qf[2][8][4];
#pragma unroll
    for (int mt = 0; mt < 2; mt++)
#pragma unroll
        for (int kb = 0; kb < 8; kb++) {
            const int rm = wm * 32 + mt * 16 + g;
            const int kk = kb * 8 + tg;
            qf[mt][kb][0] = __float_as_uint(Ps[rm * 68 + kk]);
            qf[mt][kb][1] = __float_as_uint(Ps[(rm + 8) * 68 + kk]);
            qf[mt][kb][2] = __float_as_uint(Ps[rm * 68 + kk + 4]);
            qf[mt][kb][3] = __float_as_uint(Ps[(rm + 8) * 68 + kk + 4]);
        }

    float oacc[2][4][4];
#pragma unroll
    for (int mt = 0; mt < 2; mt++)
#pragma unroll
        for (int nt = 0; nt < 4; nt++)
#pragma unroll
            for (int c = 0; c < 4; c++) oacc[mt][nt][c] = 0.f;
    float mrow[2][2] = {{-1e30f, -1e30f}, {-1e30f, -1e30f}};
    float srow[2][2] = {{0.f, 0.f}, {0.f, 0.f}};

    const int nch = (len + 63) >> 6;
    for (int kc = 0; kc < nch; kc++) {
        __syncthreads();   // prior chunk's reads of Ks/Vs/Ps done
        // load K,V chunks (tf32)
        const float* Kb = K + ((size_t)z * NS + kc * 64) * NDK;
#pragma unroll
        for (int i = 0; i < 4; i++) {
            const int idx = tid * 16 + i * 4;
            const int r = idx >> 6, c = idx & 63;
            float4 kv = *(const float4*)(Kb + r * 64 + c);
            float* dk = &Ks[r * 68 + c];
            dk[0] = tf32r(kv.x); dk[1] = tf32r(kv.y); dk[2] = tf32r(kv.z); dk[3] = tf32r(kv.w);
            float4 vv = *(const float4*)(VT + ((size_t)z * 64 + r) * NS + kc * 64 + c);
            float* dv = &Vs[r * 68 + c];
            dv[0] = tf32r(vv.x); dv[1] = tf32r(vv.y); dv[2] = tf32r(vv.z); dv[3] = tf32r(vv.w);
        }
        __syncthreads();
        // S = Q @ K^T (128 x 64)
        float sacc[2][4][4];
#pragma unroll
        for (int mt = 0; mt < 2; mt++)
#pragma unroll
            for (int nt = 0; nt < 4; nt++)
#pragma unroll
                for (int c = 0; c < 4; c++) sacc[mt][nt][c] = 0.f;
#pragma unroll
        for (int kb = 0; kb < 8; kb++) {
            const int kk = kb * 8 + tg;
            unsigned bf[4][2];
#pragma unroll
            for (int nt = 0; nt < 4; nt++) {
                const int rn = wn * 32 + nt * 8 + g;
                bf[nt][0] = __float_as_uint(Ks[rn * 68 + kk]);
                bf[nt][1] = __float_as_uint(Ks[rn * 68 + kk + 4]);
            }
#pragma unroll
            for (int mt = 0; mt < 2; mt++)
#pragma unroll
                for (int nt = 0; nt < 4; nt++)
                    mma_tf32(sacc[mt][nt], qf[mt][kb], bf[nt]);
        }
        // scale + column mask
#pragma unroll
        for (int mt = 0; mt < 2; mt++)
#pragma unroll
            for (int nt = 0; nt < 4; nt++) {
                const int col = kc * 64 + wn * 32 + nt * 8 + 2 * tg;
                const bool ok0 = col < len, ok1 = col + 1 < len;
                sacc[mt][nt][0] = ok0 ? sacc[mt][nt][0] * 0.125f : -1e30f;
                sacc[mt][nt][1] = ok1 ? sacc[mt][nt][1] * 0.125f : -1e30f;
                sacc[mt][nt][2] = ok0 ? sacc[mt][nt][2] * 0.125f : -1e30f;
                sacc[mt][nt][3] = ok1 ? sacc[mt][nt][3] * 0.125f : -1e30f;
            }
        // per-row chunk max
        float cmax[2][2] = {{-1e30f, -1e30f}, {-1e30f, -1e30f}};
#pragma unroll
        for (int mt = 0; mt < 2; mt++)
#pragma unroll
            for (int nt = 0; nt < 4; nt++) {
                cmax[mt][0] = fmaxf(cmax[mt][0], fmaxf(sacc[mt][nt][0], sacc[mt][nt][1]));
                cmax[mt][1] = fmaxf(cmax[mt][1], fmaxf(sacc[mt][nt][2], sacc[mt][nt][3]));
            }
#pragma unroll
        for (int off = 1; off < 4; off <<= 1)
#pragma unroll
            for (int mt = 0; mt < 2; mt++) {
                cmax[mt][0] = fmaxf(cmax[mt][0], __shfl_xor_sync(~0u, cmax[mt][0], off));
                cmax[mt][1] = fmaxf(cmax[mt][1], __shfl_xor_sync(~0u, cmax[mt][1], off));
            }
        if (tg == 0) {
#pragma unroll
            for (int mt = 0; mt < 2; mt++) {
                smax[wn * 128 + wm * 32 + mt * 16 + g]     = cmax[mt][0];
                smax[wn * 128 + wm * 32 + mt * 16 + 8 + g] = cmax[mt][1];
            }
        }
        __syncthreads();
        // combine across wn; update running stats; P = exp; chunk row-sums
        float alpha[2][2], csum[2][2] = {{0.f, 0.f}, {0.f, 0.f}};
#pragma unroll
        for (int mt = 0; mt < 2; mt++)
#pragma unroll
            for (int hh = 0; hh < 2; hh++) {
                const int row = wm * 32 + mt * 16 + hh * 8 + g;
                const float cm = fmaxf(smax[row], smax[128 + row]);
                const float mn = fmaxf(mrow[mt][hh], cm);
                alpha[mt][hh] = __expf(mrow[mt][hh] - mn);
                mrow[mt][hh] = mn;
            }
#pragma unroll
        for (int mt = 0; mt < 2; mt++)
#pragma unroll
            for (int nt = 0; nt < 4; nt++) {
                sacc[mt][nt][0] = __expf(sacc[mt][nt][0] - mrow[mt][0]);
                sacc[mt][nt][1] = __expf(sacc[mt][nt][1] - mrow[mt][0]);
                sacc[mt][nt][2] = __expf(sacc[mt][nt][2] - mrow[mt][1]);
                sacc[mt][nt][3] = __expf(sacc[mt][nt][3] - mrow[mt][1]);
                csum[mt][0] += sacc[mt][nt][0] + sacc[mt][nt][1];
                csum[mt][1] += sacc[mt][nt][2] + sacc[mt][nt][3];
            }
#pragma unroll
        for (int off = 1; off < 4; off <<= 1)
#pragma unroll
            for (int mt = 0; mt < 2; mt++) {
                csum[mt][0] += __shfl_xor_sync(~0u, csum[mt][0], off);
                csum[mt][1] += __shfl_xor_sync(~0u, csum[mt][1], off);
            }
        if (tg == 0) {
#pragma unroll
            for (int mt = 0; mt < 2; mt++) {
                ssum[wn * 128 + wm * 32 + mt * 16 + g]     = csum[mt][0];
                ssum[wn * 128 + wm * 32 + mt * 16 + 8 + g] = csum[mt][1];
            }
        }
        // rescale O; write P (tf32) to Ps
#pragma unroll
        for (int mt = 0; mt < 2; mt++)
#pragma unroll
            for (int nt = 0; nt < 4; nt++) {
                oacc[mt][nt][0] *= alpha[mt][0];
                oacc[mt][nt][1] *= alpha[mt][0];
                oacc[mt][nt][2] *= alpha[mt][1];
                oacc[mt][nt][3] *= alpha[mt][1];
                const int r0 = wm * 32 + mt * 16 + g;
                const int col = wn * 32 + nt * 8 + 2 * tg;
                Ps[r0 * 68 + col]           = tf32r(sacc[mt][nt][0]);
                Ps[r0 * 68 + col + 1]       = tf32r(sacc[mt][nt][1]);
                Ps[(r0 + 8) * 68 + col]     = tf32r(sacc[mt][nt][2]);
                Ps[(r0 + 8) * 68 + col + 1] = tf32r(sacc[mt][nt][3]);
            }
        __syncthreads();
#pragma unroll
        for (int mt = 0; mt < 2; mt++)
#pragma unroll
            for (int hh = 0; hh < 2; hh++) {
                const int row = wm * 32 + mt * 16 + hh * 8 + g;
                srow[mt][hh] = srow[mt][hh] * alpha[mt][hh] + ssum[row] + ssum[128 + row];
            }
        // O += P @ V^T  (contraction over the 64 chunk cols)
#pragma unroll
        for (int kb = 0; kb < 8; kb++) {
            const int kk = kb * 8 + tg;
            unsigned af[2][4], bf[4][2];
#pragma unroll
            for (int mt = 0; mt < 2; mt++) {
                const int rm = wm * 32 + mt * 16 + g;
                af[mt][0] = __float_as_uint(Ps[rm * 68 + kk]);
                af[mt][1] = __float_as_uint(Ps[(rm + 8) * 68 + kk]);
                af[mt][2] = __float_as_uint(Ps[rm * 68 + kk + 4]);
                af[mt][3] = __float_as_uint(Ps[(rm + 8) * 68 + kk + 4]);
            }
#pragma unroll
            for (int nt = 0; nt < 4; nt++) {
                const int rn = wn * 32 + nt * 8 + g;
                bf[nt][0] = __float_as_uint(Vs[rn * 68 + kk]);
                bf[nt][1] = __float_as_uint(Vs[rn * 68 + kk + 4]);
            }
#pragma unroll
            for (int mt = 0; mt < 2; mt++)
#pragma unroll
                for (int nt = 0; nt < 4; nt++)
                    mma_tf32(oacc[mt][nt], af[mt], bf[nt]);
        }
    }
    // epilogue: O / sum, zero rows q>=len, write (b, q, h*64+d)
#pragma unroll
    for (int mt = 0; mt < 2; mt++) {
        const float i0 = 1.f / srow[mt][0];
        const float i1 = 1.f / srow[mt][1];
        const int r0 = q0 + wm * 32 + mt * 16 + g;
        const bool ok0 = r0 < len, ok1 = (r0 + 8) < len;
#pragma unroll
        for (int nt = 0; nt < 4; nt++) {
            const int col = h * 64 + wn * 32 + nt * 8 + 2 * tg;
            float2 v0, v1;
            v0.x = ok0 ? oacc[mt][nt][0] * i0 : 0.f;
            v0.y = ok0 ? oacc[mt][nt][1] * i0 : 0.f;
            v1.x = ok1 ? oacc[mt][nt][2] * i1 : 0.f;
            v1.y = ok1 ? oacc[mt][nt][3] * i1 : 0.f;
            *(float2*)&CC[((size_t)b * NS + r0) * ND + col]     = v0;
            *(float2*)&CC[((size_t)b * NS + r0 + 8) * ND + col] = v1;
        }
    }
}

// ------------------------- flag reset -------------------------
__global__ void reset_kernel() {
    g_flag[blockIdx.x * 256 + threadIdx.x] = 0u;
}

// ------------------------- persistent GRU (round-7 proven version) ----------
__global__ void __launch_bounds__(384, 1) gru_kernel(
    const float* __restrict__ whf, const float* __restrict__ whb,
    const float* __restrict__ bhf, const float* __restrict__ bhb,
    const int* __restrict__ masks, float* __restrict__ hid_out)
{
    __shared__ float sh_h[1024];
    __shared__ float sh_gate[384];

    const int bid = blockIdx.x;
    const int dir = bid >> 6;
    const int rem = bid & 63;
    const int bg  = rem >> 3;
    const int jc  = rem & 7;
    const int grp = dir * 8 + bg;
    const int tid = threadIdx.x;
    const int rg  = tid >> 3;
    const int ks  = tid & 7;
    const int row0 = rg * 2, row1 = rg * 2 + 1;
    const int G0 = (row0 >> 5) * 256 + jc * 32 + (row0 & 31);
    const int G1 = (row1 >> 5) * 256 + jc * 32 + (row1 & 31);

    const float* wh = dir ? whb : whf;
    const float* bh = dir ? bhb : bhf;
    const float bh0 = bh[G0], bh1 = bh[G1];

    unsigned long long wp0[16], wp1[16];
    {
        const float* w0s = wh + (long)G0 * NH2 + ks * 32;
        const float* w1s = wh + (long)G1 * NH2 + ks * 32;
#pragma unroll
        for (int i = 0; i < 16; i++) {
            wp0[i] = pack2(w0s[2 * i], w0s[2 * i + 1]);
            wp1[i] = pack2(w1s[2 * i], w1s[2 * i + 1]);
        }
    }

    const int ju = tid & 31, bu = tid >> 5;
    const int jglob = jc * 32 + ju;
    const int bglob = bg * 4 + bu;
    const float* xgp = g_xg + ((size_t)dir * NB + bglob) * NS * NG3;
    float* hxg = g_hx + grp * 2048;
    unsigned* myflag = &g_flag[(grp * 8 + jc) * 32];

    const int cb = tid >> 6, cc0 = tid & 63;
    const int csw = ((cc0 >> 3) << 3) | ((cc0 & 7) ^ (cc0 >> 3));
    float* shdst = &sh_h[cb * 256 + csw * 4];

    for (int i = tid; i < 1024; i += 384) sh_h[i] = 0.f;
    float hreg = 0.f;
    __syncthreads();

    for (int t = 0; t < NS; t++) {
        const int s = dir ? (NS - 1 - t) : t;
        float xr = 0.f, xz = 0.f, xn = 0.f;
        int mk = 0;
        if (tid < 128) {
            const float* xrow = xgp + (size_t)s * NG3;
            xr = __ldg(xrow + jglob);
            xz = __ldg(xrow + NH2 + jglob);
            xn = __ldg(xrow + 2 * NH2 + jglob);
            mk = __ldg(masks + bglob * NS + s);
        }
        if (t > 0) {
            if (tid < 8) {
                const unsigned* fp = &g_flag[(grp * 8 + tid) * 32];
                unsigned v;
                do {
                    asm volatile("ld.global.acquire.gpu.u32 %0, [%1];"
                                 : "=r"(v) : "l"(fp) : "memory");
                } while (v < (unsigned)t);
            }
            __syncthreads();
            if (tid < 256) {
                const float4* src = (const float4*)(hxg + ((t - 1) & 1) * 1024);
                float4 hv4;
                asm volatile("ld.global.cg.v4.f32 {%0,%1,%2,%3}, [%4];"
                             : "=f"(hv4.x), "=f"(hv4.y), "=f"(hv4.z), "=f"(hv4.w)
                             : "l"(src + tid) : "memory");
                *(float4*)shdst = hv4;
            }
            __syncthreads();
        }
        unsigned long long a0[4] = {0ull, 0ull, 0ull, 0ull};
        unsigned long long a1[4] = {0ull, 0ull, 0ull, 0ull};
#pragma unroll
        for (int i = 0; i < 8; i++) {
            const int coff = (((ks << 3) | (i ^ ks)) << 2);
#pragma unroll
            for (int b = 0; b < 4; b++) {
                ulonglong2 hv = *(const ulonglong2*)(sh_h + b * 256 + coff);
                a0[b] = fma2(wp0[2 * i],     hv.x, a0[b]);
                a0[b] = fma2(wp0[2 * i + 1], hv.y, a0[b]);
                a1[b] = fma2(wp1[2 * i],     hv.x, a1[b]);
                a1[b] = fma2(wp1[2 * i + 1], hv.y, a1[b]);
            }
        }
        float v0[4], v1[4];
#pragma unroll
        for (int b = 0; b < 4; b++) {
            float lo, hi;
            unpack2(a0[b], lo, hi); v0[b] = lo + hi;
            unpack2(a1[b], lo, hi); v1[b] = lo + hi;
        }
#pragma unroll
        for (int off = 1; off < 8; off <<= 1) {
#pragma unroll
            for (int b = 0; b < 4; b++) {
                v0[b] += __shfl_xor_sync(~0u, v0[b], off);
                v1[b] += __shfl_xor_sync(~0u, v1[b], off);
            }
        }
        if (ks == 0) {
            float4 f0 = make_float4(v0[0] + bh0, v0[1] + bh0, v0[2] + bh0, v0[3] + bh0);
            float4 f1 = make_float4(v1[0] + bh1, v1[1] + bh1, v1[2] + bh1, v1[3] + bh1);
            *(float4*)&sh_gate[rg * 8]     = f0;
            *(float4*)&sh_gate[rg * 8 + 4] = f1;
        }
        __syncthreads();
        if (tid < 128) {
            const float hgr = sh_gate[ju * 4 + bu];
            const float hgz = sh_gate[(32 + ju) * 4 + bu];
            const float hgn = sh_gate[(64 + ju) * 4 + bu];
            const float rr = 1.f / (1.f + __expf(-(xr + hgr)));
            const float zz = 1.f / (1.f + __expf(-(xz + hgz)));
            const float na = xn + rr * hgn;
            const float nn = 2.f / (1.f + __expf(-2.f * na)) - 1.f;
            const float hnew = (1.f - zz) * nn + zz * hreg;
            hreg = mk ? hnew : hreg;
            g_gru[((size_t)bglob * NS + s) * ND + dir * NH2 + jglob] = mk ? hreg : 0.f;
            if (t == NS - 1) {
                hid_out[bglob * ND + dir * NH2 + jglob] = hreg;
            } else {
                __stcg(hxg + (t & 1) * 1024 + bu * 256 + jglob, hreg);
            }
        }
        if (t < NS - 1) {
            __syncthreads();
            if (tid == 0) {
                __threadfence();
                unsigned nv = (unsigned)(t + 1);
                asm volatile("st.global.cg.u32 [%0], %1;"
                             :: "l"(myflag), "r"(nv) : "memory");
            }
        }
    }
}

// ------------------------- layernorm (optionally fused residual) ------------
__global__ void __launch_bounds__(128) ln_kernel(
    const float* __restrict__ x, const float* __restrict__ y,
    const float* __restrict__ gam, const float* __restrict__ bet,
    float* __restrict__ out)
{
    __shared__ float red[8];
    const int row = blockIdx.x;
    const int tid = threadIdx.x;
    float4 v = *(const float4*)(x + (size_t)row * ND + tid * 4);
    if (y) {
        float4 w = *(const float4*)(y + (size_t)row * ND + tid * 4);
        v.x += w.x; v.y += w.y; v.z += w.z; v.w += w.w;
    }
    float s1 = v.x + v.y + v.z + v.w;
    float s2 = v.x * v.x + v.y * v.y + v.z * v.z + v.w * v.w;
#pragma unroll
    for (int o = 16; o; o >>= 1) {
        s1 += __shfl_xor_sync(~0u, s1, o);
        s2 += __shfl_xor_sync(~0u, s2, o);
    }
    const int wid = tid >> 5;
    if ((tid & 31) == 0) { red[wid] = s1; red[wid + 4] = s2; }
    __syncthreads();
    s1 = red[0] + red[1] + red[2] + red[3];
    s2 = red[4] + red[5] + red[6] + red[7];
    const float mu = s1 * (1.f / ND);
    const float var = s2 * (1.f / ND) - mu * mu;
    const float rs = rsqrtf(var + 1e-5f);
    const float4 gv = *(const float4*)(gam + tid * 4);
    const float4 bv = *(const float4*)(bet + tid * 4);
    float4 o4;
    o4.x = (v.x - mu) * rs * gv.x + bv.x;
    o4.y = (v.y - mu) * rs * gv.y + bv.y;
    o4.z = (v.z - mu) * rs * gv.z + bv.z;
    o4.w = (v.w - mu) * rs * gv.w + bv.w;
    *(float4*)(out + (size_t)row * ND + tid * 4) = o4;
}

// ------------------------- launch -------------------------
extern "C" void kernel_launch(void* const* d_in, const int* in_sizes, int n_in,
                              void* d_out, int out_size)
{
    const float* splits = (const float*)d_in[0];
    const float* w_ih_f = (const float*)d_in[1];
    const float* w_hh_f = (const float*)d_in[2];
    const float* b_ih_f = (const float*)d_in[3];
    const float* b_hh_f = (const float*)d_in[4];
    const float* w_ih_b = (const float*)d_in[5];
    const float* w_hh_b = (const float*)d_in[6];
    const float* b_ih_b = (const float*)d_in[7];
    const float* b_hh_b = (const float*)d_in[8];
    const float* ln1_g  = (const float*)d_in[9];
    const float* ln1_b  = (const float*)d_in[10];
    const float* wq = (const float*)d_in[11];
    const float* bq = (const float*)d_in[12];
    const float* wk = (const float*)d_in[13];
    const float* bk = (const float*)d_in[14];
    const float* wv = (const float*)d_in[15];
    const float* bv = (const float*)d_in[16];
    const float* wo = (const float*)d_in[17];
    const float* bo = (const float*)d_in[18];
    const float* ln2_g = (const float*)d_in[19];
    const float* ln2_b = (const float*)d_in[20];
    const int* lengths = (const int*)d_in[21];
    const int* masks   = (const int*)d_in[22];
    float* out = (float*)d_out;

    float *xg, *gru, *ln1, *q, *k, *vt, *cc, *oo;
    cudaGetSymbolAddress((void**)&xg,  g_xg);
    cudaGetSymbolAddress((void**)&gru, g_gru);
    cudaGetSymbolAddress((void**)&ln1, g_ln1);
    cudaGetSymbolAddress((void**)&q,   g_q);
    cudaGetSymbolAddress((void**)&k,   g_k);
    cudaGetSymbolAddress((void**)&vt,  g_vt);
    cudaGetSymbolAddress((void**)&cc,  g_cc);
    cudaGetSymbolAddress((void**)&oo,  g_o);

    const int M = NB * NS;  // 16384
    const int ATTN_SMEM = ATTN_SMEM_FLOATS * 4;
    cudaFuncSetAttribute(attn_kernel, cudaFuncAttributeMaxDynamicSharedMemorySize, ATTN_SMEM);

    // GRU input projections (both dirs) — tf32 tensor cores
    gemm_tf32<<<dim3(6, 128), 256>>>(splits, w_ih_f, b_ih_f, xg,
                                     M, NG3, ND, 0, 1.f, nullptr);
    gemm_tf32<<<dim3(6, 128), 256>>>(splits, w_ih_b, b_ih_b, xg + (size_t)M * NG3,
                                     M, NG3, ND, 0, 1.f, nullptr);
    // GRU recurrence (persistent, per-rank flag sync through L2)
    reset_kernel<<<16, 256>>>();
    gru_kernel<<<128, 384>>>(w_hh_f, w_hh_b, b_hh_f, b_hh_b, masks,
                             out + (size_t)NB * NS * ND);
    // LN1
    ln_kernel<<<M, 128>>>(gru, nullptr, ln1_g, ln1_b, ln1);
    // Q/K/V projections with head scatter — tf32
    gemm_tf32<<<dim3(4, 128), 256>>>(ln1, wq, bq, q,  M, ND, ND, 1, 1.f, nullptr);
    gemm_tf32<<<dim3(4, 128), 256>>>(ln1, wk, bk, k,  M, ND, ND, 1, 1.f, nullptr);
    gemm_tf32<<<dim3(4, 128), 256>>>(ln1, wv, bv, vt, M, ND, ND, 2, 1.f, nullptr);
    // fused attention: scores + masked online softmax + PV -> concat
    attn_kernel<<<dim3(4, 256), 256, ATTN_SMEM>>>(q, k, vt, cc, lengths);
    // out projection + row mask — tf32
    gemm_tf32<<<dim3(4, 128), 256>>>(cc, wo, bo, oo, M, ND, ND, 5, 1.f, masks);
    // residual + LN2 -> final outputs
    ln_kernel<<<M, 128>>>(ln1, oo, ln2_g, ln2_b, out);
}

// round 13
// speedup vs baseline: 2.1218x; 1.0270x over previous
#include <cuda_runtime.h>
#include <cstdint>
#include <cstddef>

#define NB   32
#define NS   512
#define ND   512
#define NH2  256
#define NG3  768
#define NDK  64

// ------------------------- scratch (device globals) -------------------------
__device__ float g_xg[(size_t)2 * NB * NS * NG3];   // gate preactivations, per dir
__device__ float g_gru[(size_t)NB * NS * ND];       // concat GRU outputs
__device__ float g_ln1[(size_t)NB * NS * ND];       // ln1("outputs")
__device__ float g_q [(size_t)NB * 8 * NS * NDK];   // (b,h,s,d)
__device__ float g_k [(size_t)NB * 8 * NS * NDK];   // (b,h,s,d)
__device__ float g_vt[(size_t)NB * 8 * NDK * NS];   // (b,h,d,s)
__device__ float g_cc[(size_t)NB * NS * ND];        // attn concat
__device__ float g_o [(size_t)NB * NS * ND];        // out projection
__device__ float g_hx[16 * 2048];                   // h exchange (16 groups x 2 bufs x 1024)
__device__ unsigned g_flag[16 * 8 * 32];            // per (group,rank) step flag, 1 per 128B line

// ------------------------- f32x2 helpers -------------------------
__device__ __forceinline__ unsigned long long fma2(unsigned long long a,
                                                   unsigned long long b,
                                                   unsigned long long c) {
    unsigned long long d;
    asm("fma.rn.f32x2 %0, %1, %2, %3;" : "=l"(d) : "l"(a), "l"(b), "l"(c));
    return d;
}
__device__ __forceinline__ unsigned long long pack2(float x, float y) {
    unsigned long long d;
    asm("mov.b64 %0, {%1, %2};" : "=l"(d) : "f"(x), "f"(y));
    return d;
}
__device__ __forceinline__ void unpack2(unsigned long long v, float& x, float& y) {
    asm("mov.b64 {%0, %1}, %2;" : "=f"(x), "=f"(y) : "l"(v));
}
__device__ __forceinline__ float tf32r(float f) {
    unsigned u;
    asm("cvt.rna.tf32.f32 %0, %1;" : "=r"(u) : "f"(f));
    return __uint_as_float(u);
}
__device__ __forceinline__ void mma_tf32(float* acc, const unsigned* a, const unsigned* b) {
    asm volatile(
        "mma.sync.aligned.m16n8k8.row.col.f32.tf32.tf32.f32 "
        "{%0,%1,%2,%3}, {%4,%5,%6,%7}, {%8,%9}, {%0,%1,%2,%3};"
        : "+f"(acc[0]), "+f"(acc[1]), "+f"(acc[2]), "+f"(acc[3])
        : "r"(a[0]), "r"(a[1]), "r"(a[2]), "r"(a[3]),
          "r"(b[0]), "r"(b[1]));
}

// ------------------------- epilogue store -------------------------
// 0: +bias   1: +bias, scatter (b,h,s,d)   2: +bias, scatter (b,h,d,s)
// 5: +bias, *rowmask(masks)
__device__ __forceinline__ void store_elem(float* C, const float* bias,
                                           const int* masks, int mode,
                                           int N, int mrow, int nc, float v) {
    if (mode == 0) {
        C[(size_t)mrow * N + nc] = v + bias[nc];
    } else if (mode == 1) {
        int b = mrow >> 9, s = mrow & 511, h = nc >> 6, d = nc & 63;
        C[(((size_t)(b * 8 + h) * NS + s)) * NDK + d] = v + bias[nc];
    } else if (mode == 2) {
        int b = mrow >> 9, s = mrow & 511, h = nc >> 6, d = nc & 63;
        C[((size_t)(b * 8 + h) * NDK + d) * NS + s] = v + bias[nc];
    } else {
        C[(size_t)mrow * N + nc] = masks[mrow] ? (v + bias[nc]) : 0.f;
    }
}

// ------------------------- tf32 TN GEMM, double-buffered, up to 3 ops/z -----
// C = epi(A[M,K] @ W[N,K]^T). Requires M%128==0, N%128==0, K%32==0.
// 128x128x32 tile, 2-stage smem pipeline, 1 syncthreads per K-chunk.
#define G3_SMEM (2 * 2 * 128 * 36 * 4)
__global__ void __launch_bounds__(256) gemm3(
    const float* __restrict__ A,
    const float* __restrict__ W0, const float* __restrict__ W1, const float* __restrict__ W2,
    const float* __restrict__ b0, const float* __restrict__ b1, const float* __restrict__ b2,
    float* __restrict__ C0, float* __restrict__ C1, float* __restrict__ C2,
    int mode0, int mode1, int mode2,
    int M, int N, int K, const int* __restrict__ masks)
{
    extern __shared__ float smg[];
    float* Asm = smg;                 // [2][128][36]
    float* Wsm = smg + 2 * 128 * 36;  // [2][128][36]

    const int z = blockIdx.z;
    const float* W    = (z == 0) ? W0 : (z == 1) ? W1 : W2;
    const float* bias = (z == 0) ? b0 : (z == 1) ? b1 : b2;
    float* C          = (z == 0) ? C0 : (z == 1) ? C1 : C2;
    const int mode    = (z == 0) ? mode0 : (z == 1) ? mode1 : mode2;

    const int m0 = blockIdx.y * 128, n0 = blockIdx.x * 128;
    const int tid  = threadIdx.x;
    const int warp = tid >> 5, lane = tid & 31;
    const int wm = warp >> 2, wn = warp & 3;     // warp grid 2 x 4 (64x32 each)
    const int g  = lane >> 2, tg = lane & 3;

    // loader: row 0..127, half lkq covers 16 consecutive k
    const int lrow = tid >> 1, lkq = tid & 1;
    const float* Ap = A + (size_t)(m0 + lrow) * K + lkq * 16;
    const float* Wp = W + (size_t)(n0 + lrow) * K + lkq * 16;
    const int dsto = lrow * 36 + lkq * 16;

    float acc[4][4][4];
#pragma unroll
    for (int mt = 0; mt < 4; mt++)
#pragma unroll
        for (int nt = 0; nt < 4; nt++)
#pragma unroll
            for (int c = 0; c < 4; c++) acc[mt][nt][c] = 0.f;

    float4 ar[4], wr[4];
#pragma unroll
    for (int i = 0; i < 4; i++) {
        ar[i] = *(const float4*)(Ap + i * 4);
        wr[i] = *(const float4*)(Wp + i * 4);
    }
#pragma unroll
    for (int i = 0; i < 4; i++) {
        float4 c;
        c.x = tf32r(ar[i].x); c.y = tf32r(ar[i].y);
        c.z = tf32r(ar[i].z); c.w = tf32r(ar[i].w);
        *(float4*)(Asm + dsto + i * 4) = c;
        c.x = tf32r(wr[i].x); c.y = tf32r(wr[i].y);
        c.z = tf32r(wr[i].z); c.w = tf32r(wr[i].w);
        *(float4*)(Wsm + dsto + i * 4) = c;
    }
    __syncthreads();

    const int niter = K >> 5;
    int p = 0;
    for (int it = 0; it < niter; ++it) {
        if (it + 1 < niter) {
            const int ko = (it + 1) << 5;
#pragma unroll
            for (int i = 0; i < 4; i++) {
                ar[i] = *(const float4*)(Ap + ko + i * 4);
                wr[i] = *(const float4*)(Wp + ko + i * 4);
            }
        }
        const float* ab = Asm + p * (128 * 36);
        const float* wb = Wsm + p * (128 * 36);
#pragma unroll
        for (int kb = 0; kb < 4; kb++) {
            const int kk = kb * 8 + tg;
            unsigned a[4][4], b[4][2];
#pragma unroll
            for (int mt = 0; mt < 4; mt++) {
                const int rm = wm * 64 + mt * 16 + g;
                a[mt][0] = __float_as_uint(ab[rm * 36 + kk]);
                a[mt][1] = __float_as_uint(ab[(rm + 8) * 36 + kk]);
                a[mt][2] = __float_as_uint(ab[rm * 36 + kk + 4]);
                a[mt][3] = __float_as_uint(ab[(rm + 8) * 36 + kk + 4]);
            }
#pragma unroll
            for (int nt = 0; nt < 4; nt++) {
                const int rn = wn * 32 + nt * 8 + g;
                b[nt][0] = __float_as_uint(wb[rn * 36 + kk]);
                b[nt][1] = __float_as_uint(wb[rn * 36 + kk + 4]);
            }
#pragma unroll
            for (int mt = 0; mt < 4; mt++)
#pragma unroll
                for (int nt = 0; nt < 4; nt++)
                    mma_tf32(acc[mt][nt], a[mt], b[nt]);
        }
        if (it + 1 < niter) {
            float* ad = Asm + (p ^ 1) * (128 * 36) + dsto;
            float* wd = Wsm + (p ^ 1) * (128 * 36) + dsto;
#pragma unroll
            for (int i = 0; i < 4; i++) {
                float4 c;
                c.x = tf32r(ar[i].x); c.y = tf32r(ar[i].y);
                c.z = tf32r(ar[i].z); c.w = tf32r(ar[i].w);
                *(float4*)(ad + i * 4) = c;
                c.x = tf32r(wr[i].x); c.y = tf32r(wr[i].y);
                c.z = tf32r(wr[i].z); c.w = tf32r(wr[i].w);
                *(float4*)(wd + i * 4) = c;
            }
        }
        __syncthreads();
        p ^= 1;
    }

#pragma unroll
    for (int mt = 0; mt < 4; mt++) {
#pragma unroll
        for (int nt = 0; nt < 4; nt++) {
            const int row0 = m0 + wm * 64 + mt * 16 + g;
            const int col0 = n0 + wn * 32 + nt * 8 + 2 * tg;
            store_elem(C, bias, masks, mode, N, row0,     col0,     acc[mt][nt][0]);
            store_elem(C, bias, masks, mode, N, row0,     col0 + 1, acc[mt][nt][1]);
            store_elem(C, bias, masks, mode, N, row0 + 8, col0,     acc[mt][nt][2]);
            store_elem(C, bias, masks, mode, N, row0 + 8, col0 + 1, acc[mt][nt][3]);
        }
    }
}

// ------------------------- fused attention (scores+softmax+PV) --------------
#define ATTN_SMEM_FLOATS (128*68 + 64*68 + 64*68 + 256 + 256)
__global__ void __launch_bounds__(256) attn_kernel(
    const float* __restrict__ Q, const float* __restrict__ K,
    const float* __restrict__ VT, float* __restrict__ CC,
    const int* __restrict__ lengths)
{
    extern __shared__ float sm[];
    float* Ps   = sm;
    float* Ks   = sm + 128 * 68;
    float* Vs   = Ks + 64 * 68;
    float* smax = Vs + 64 * 68;
    float* ssum = smax + 256;

    const int qt = blockIdx.x, z = blockIdx.y;
    const int b = z >> 3, h = z & 7;
    const int q0 = qt * 128;
    const int len = __ldg(lengths + b);
    const int tid = threadIdx.x;
    const int warp = tid >> 5, lane = tid & 31;
    const int wm = warp >> 1, wn = warp & 1;
    const int g = lane >> 2, tg = lane & 3;

    const float* Qb = Q + ((size_t)z * NS + q0) * NDK;
#pragma unroll
    for (int i = 0; i < 8; i++) {
        const int idx = tid * 32 + i * 4;
        const int r = idx >> 6, c = idx & 63;
        float4 v = *(const float4*)(Qb + r * 64 + c);
        float* d = &Ps[r * 68 + c];
        d[0] = tf32r(v.x); d[1] = tf32r(v.y); d[2] = tf32r(v.z); d[3] = tf32r(v.w);
    }
    __syncthreads();

    unsigned qf[2][8][4];
#pragma unroll
    for (int mt = 0; mt < 2; mt++)
#pragma unroll
        for (int kb = 0; kb < 8; kb++) {
            const int rm = wm * 32 + mt * 16 + g;
            const int kk = kb * 8 + tg;
            qf[mt][kb][0] = __float_as_uint(Ps[rm * 68 + kk]);
            qf[mt][kb][1] = __float_as_uint(Ps[(rm + 8) * 68 + kk]);
            qf[mt][kb][2] = __float_as_uint(Ps[rm * 68 + kk + 4]);
            qf[mt][kb][3] = __float_as_uint(Ps[(rm + 8) * 68 + kk + 4]);
        }

    float oacc[2][4][4];
#pragma unroll
    for (int mt = 0; mt < 2; mt++)
#pragma unroll
        for (int nt = 0; nt < 4; nt++)
#pragma unroll
            for (int c = 0; c < 4; c++) oacc[mt][nt][c] = 0.f;
    float mrow[2][2] = {{-1e30f, -1e30f}, {-1e30f, -1e30f}};
    float srow[2][2] = {{0.f, 0.f}, {0.f, 0.f}};

    const int nch = (len + 63) >> 6;
    for (int kc = 0; kc < nch; kc++) {
        __syncthreads();
        const float* Kb = K + ((size_t)z * NS + kc * 64) * NDK;
#pragma unroll
        for (int i = 0; i < 4; i++) {
            const int idx = tid * 16 + i * 4;
            const int r = idx >> 6, c = idx & 63;
            float4 kv = *(const float4*)(Kb + r * 64 + c);
            float* dk = &Ks[r * 68 + c];
            dk[0] = tf32r(kv.x); dk[1] = tf32r(kv.y); dk[2] = tf32r(kv.z); dk[3] = tf32r(kv.w);
            float4 vv = *(const float4*)(VT + ((size_t)z * 64 + r) * NS + kc * 64 + c);
            float* dv = &Vs[r * 68 + c];
            dv[0] = tf32r(vv.x); dv[1] = tf32r(vv.y); dv[2] = tf32r(vv.z); dv[3] = tf32r(vv.w);
        }
        __syncthreads();
        float sacc[2][4][4];
#pragma unroll
        for (int mt = 0; mt < 2; mt++)
#pragma unroll
            for (int nt = 0; nt < 4; nt++)
#pragma unroll
                for (int c = 0; c < 4; c++) sacc[mt][nt][c] = 0.f;
#pragma unroll
        for (int kb = 0; kb < 8; kb++) {
            const int kk = kb * 8 + tg;
            unsigned bf[4][2];
#pragma unroll
            for (int nt = 0; nt < 4; nt++) {
                const int rn = wn * 32 + nt * 8 + g;
                bf[nt][0] = __float_as_uint(Ks[rn * 68 + kk]);
                bf[nt][1] = __float_as_uint(Ks[rn * 68 + kk + 4]);
            }
#pragma unroll
            for (int mt = 0; mt < 2; mt++)
#pragma unroll
                for (int nt = 0; nt < 4; nt++)
                    mma_tf32(sacc[mt][nt], qf[mt][kb], bf[nt]);
        }
#pragma unroll
        for (int mt = 0; mt < 2; mt++)
#pragma unroll
            for (int nt = 0; nt < 4; nt++) {
                const int col = kc * 64 + wn * 32 + nt * 8 + 2 * tg;
                const bool ok0 = col < len, ok1 = col + 1 < len;
                sacc[mt][nt][0] = ok0 ? sacc[mt][nt][0] * 0.125f : -1e30f;
                sacc[mt][nt][1] = ok1 ? sacc[mt][nt][1] * 0.125f : -1e30f;
                sacc[mt][nt][2] = ok0 ? sacc[mt][nt][2] * 0.125f : -1e30f;
                sacc[mt][nt][3] = ok1 ? sacc[mt][nt][3] * 0.125f : -1e30f;
            }
        float cmax[2][2] = {{-1e30f, -1e30f}, {-1e30f, -1e30f}};
#pragma unroll
        for (int mt = 0; mt < 2; mt++)
#pragma unroll
            for (int nt = 0; nt < 4; nt++) {
                cmax[mt][0] = fmaxf(cmax[mt][0], fmaxf(sacc[mt][nt][0], sacc[mt][nt][1]));
                cmax[mt][1] = fmaxf(cmax[mt][1], fmaxf(sacc[mt][nt][2], sacc[mt][nt][3]));
            }
#pragma unroll
        for (int off = 1; off < 4; off <<= 1)
#pragma unroll
            for (int mt = 0; mt < 2; mt++) {
                cmax[mt][0] = fmaxf(cmax[mt][0], __shfl_xor_sync(~0u, cmax[mt][0], off));
                cmax[mt][1] = fmaxf(cmax[mt][1], __shfl_xor_sync(~0u, cmax[mt][1], off));
            }
        if (tg == 0) {
#pragma unroll
            for (int mt = 0; mt < 2; mt++) {
                smax[wn * 128 + wm * 32 + mt * 16 + g]     = cmax[mt][0];
                smax[wn * 128 + wm * 32 + mt * 16 + 8 + g] = cmax[mt][1];
            }
        }
        __syncthreads();
        float alpha[2][2], csum[2][2] = {{0.f, 0.f}, {0.f, 0.f}};
#pragma unroll
        for (int mt = 0; mt < 2; mt++)
#pragma unroll
            for (int hh = 0; hh < 2; hh++) {
                const int row = wm * 32 + mt * 16 + hh * 8 + g;
                const float cm = fmaxf(smax[row], smax[128 + row]);
                const float mn = fmaxf(mrow[mt][hh], cm);
                alpha[mt][hh] = __expf(mrow[mt][hh] - mn);
                mrow[mt][hh] = mn;
            }
#pragma unroll
        for (int mt = 0; mt < 2; mt++)
#pragma unroll
            for (int nt = 0; nt < 4; nt++) {
                sacc[mt][nt][0] = __expf(sacc[mt][nt][0] - mrow[mt][0]);
                sacc[mt][nt][1] = __expf(sacc[mt][nt][1] - mrow[mt][0]);
                sacc[mt][nt][2] = __expf(sacc[mt][nt][2] - mrow[mt][1]);
                sacc[mt][nt][3] = __expf(sacc[mt][nt][3] - mrow[mt][1]);
                csum[mt][0] += sacc[mt][nt][0] + sacc[mt][nt][1];
                csum[mt][1] += sacc[mt][nt][2] + sacc[mt][nt][3];
            }
#pragma unroll
        for (int off = 1; off < 4; off <<= 1)
#pragma unroll
            for (int mt = 0; mt < 2; mt++) {
                csum[mt][0] += __shfl_xor_sync(~0u, csum[mt][0], off);
                csum[mt][1] += __shfl_xor_sync(~0u, csum[mt][1], off);
            }
        if (tg == 0) {
#pragma unroll
            for (int mt = 0; mt < 2; mt++) {
                ssum[wn * 128 + wm * 32 + mt * 16 + g]     = csum[mt][0];
                ssum[wn * 128 + wm * 32 + mt * 16 + 8 + g] = csum[mt][1];
            }
        }
#pragma unroll
        for (int mt = 0; mt < 2; mt++)
#pragma unroll
            for (int nt = 0; nt < 4; nt++) {
                oacc[mt][nt][0] *= alpha[mt][0];
                oacc[mt][nt][1] *= alpha[mt][0];
                oacc[mt][nt][2] *= alpha[mt][1];
                oacc[mt][nt][3] *= alpha[mt][1];
                const int r0 = wm * 32 + mt * 16 + g;
                const int col = wn * 32 + nt * 8 + 2 * tg;
                Ps[r0 * 68 + col]           = tf32r(sacc[mt][nt][0]);
                Ps[r0 * 68 + col + 1]       = tf32r(sacc[mt][nt][1]);
                Ps[(r0 + 8) * 68 + col]     = tf32r(sacc[mt][nt][2]);
                Ps[(r0 + 8) * 68 + col + 1] = tf32r(sacc[mt][nt][3]);
            }
        __syncthreads();
#pragma unroll
        for (int mt = 0; mt < 2; mt++)
#pragma unroll
            for (int hh = 0; hh < 2; hh++) {
                const int row = wm * 32 + mt * 16 + hh * 8 + g;
                srow[mt][hh] = srow[mt][hh] * alpha[mt][hh] + ssum[row] + ssum[128 + row];
            }
#pragma unroll
        for (int kb = 0; kb < 8; kb++) {
            const int kk = kb * 8 + tg;
            unsigned af[2][4], bf[4][2];
#pragma unroll
            for (int mt = 0; mt < 2; mt++) {
                const int rm = wm * 32 + mt * 16 + g;
                af[mt][0] = __float_as_uint(Ps[rm * 68 + kk]);
                af[mt][1] = __float_as_uint(Ps[(rm + 8) * 68 + kk]);
                af[mt][2] = __float_as_uint(Ps[rm * 68 + kk + 4]);
                af[mt][3] = __float_as_uint(Ps[(rm + 8) * 68 + kk + 4]);
            }
#pragma unroll
            for (int nt = 0; nt < 4; nt++) {
                const int rn = wn * 32 + nt * 8 + g;
                bf[nt][0] = __float_as_uint(Vs[rn * 68 + kk]);
                bf[nt][1] = __float_as_uint(Vs[rn * 68 + kk + 4]);
            }
#pragma unroll
            for (int mt = 0; mt < 2; mt++)
#pragma unroll
                for (int nt = 0; nt < 4; nt++)
                    mma_tf32(oacc[mt][nt], af[mt], bf[nt]);
        }
    }
#pragma unroll
    for (int mt = 0; mt < 2; mt++) {
        const float i0 = 1.f / srow[mt][0];
        const float i1 = 1.f / srow[mt][1];
        const int r0 = q0 + wm * 32 + mt * 16 + g;
        const bool ok0 = r0 < len, ok1 = (r0 + 8) < len;
#pragma unroll
        for (int nt = 0; nt < 4; nt++) {
            const int col = h * 64 + wn * 32 + nt * 8 + 2 * tg;
            float2 v0, v1;
            v0.x = ok0 ? oacc[mt][nt][0] * i0 : 0.f;
            v0.y = ok0 ? oacc[mt][nt][1] * i0 : 0.f;
            v1.x = ok1 ? oacc[mt][nt][2] * i1 : 0.f;
            v1.y = ok1 ? oacc[mt][nt][3] * i1 : 0.f;
            *(float2*)&CC[((size_t)b * NS + r0) * ND + col]     = v0;
            *(float2*)&CC[((size_t)b * NS + r0 + 8) * ND + col] = v1;
        }
    }
}

// ------------------------- flag reset -------------------------
__global__ void reset_kernel() {
    g_flag[blockIdx.x * 256 + threadIdx.x] = 0u;
}

// ------------------------- persistent GRU (round-7 proven version) ----------
__global__ void __launch_bounds__(384, 1) gru_kernel(
    const float* __restrict__ whf, const float* __restrict__ whb,
    const float* __restrict__ bhf, const float* __restrict__ bhb,
    const int* __restrict__ masks, float* __restrict__ hid_out)
{
    __shared__ float sh_h[1024];
    __shared__ float sh_gate[384];

    const int bid = blockIdx.x;
    const int dir = bid >> 6;
    const int rem = bid & 63;
    const int bg  = rem >> 3;
    const int jc  = rem & 7;
    const int grp = dir * 8 + bg;
    const int tid = threadIdx.x;
    const int rg  = tid >> 3;
    const int ks  = tid & 7;
    const int row0 = rg * 2, row1 = rg * 2 + 1;
    const int G0 = (row0 >> 5) * 256 + jc * 32 + (row0 & 31);
    const int G1 = (row1 >> 5) * 256 + jc * 32 + (row1 & 31);

    const float* wh = dir ? whb : whf;
    const float* bh = dir ? bhb : bhf;
    const float bh0 = bh[G0], bh1 = bh[G1];

    unsigned long long wp0[16], wp1[16];
    {
        const float* w0s = wh + (long)G0 * NH2 + ks * 32;
        const float* w1s = wh + (long)G1 * NH2 + ks * 32;
#pragma unroll
        for (int i = 0; i < 16; i++) {
            wp0[i] = pack2(w0s[2 * i], w0s[2 * i + 1]);
            wp1[i] = pack2(w1s[2 * i], w1s[2 * i + 1]);
        }
    }

    const int ju = tid & 31, bu = tid >> 5;
    const int jglob = jc * 32 + ju;
    const int bglob = bg * 4 + bu;
    const float* xgp = g_xg + ((size_t)dir * NB + bglob) * NS * NG3;
    float* hxg = g_hx + grp * 2048;
    unsigned* myflag = &g_flag[(grp * 8 + jc) * 32];

    const int cb = tid >> 6, cc0 = tid & 63;
    const int csw = ((cc0 >> 3) << 3) | ((cc0 & 7) ^ (cc0 >> 3));
    float* shdst = &sh_h[cb * 256 + csw * 4];

    for (int i = tid; i < 1024; i += 384) sh_h[i] = 0.f;
    float hreg = 0.f;
    __syncthreads();

    for (int t = 0; t < NS; t++) {
        const int s = dir ? (NS - 1 - t) : t;
        float xr = 0.f, xz = 0.f, xn = 0.f;
        int mk = 0;
        if (tid < 128) {
            const float* xrow = xgp + (size_t)s * NG3;
            xr = __ldg(xrow + jglob);
            xz = __ldg(xrow + NH2 + jglob);
            xn = __ldg(xrow + 2 * NH2 + jglob);
            mk = __ldg(masks + bglob * NS + s);
        }
        if (t > 0) {
            if (tid < 8) {
                const unsigned* fp = &g_flag[(grp * 8 + tid) * 32];
                unsigned v;
                do {
                    asm volatile("ld.global.acquire.gpu.u32 %0, [%1];"
                                 : "=r"(v) : "l"(fp) : "memory");
                } while (v < (unsigned)t);
            }
            __syncthreads();
            if (tid < 256) {
                const float4* src = (const float4*)(hxg + ((t - 1) & 1) * 1024);
                float4 hv4;
                asm volatile("ld.global.cg.v4.f32 {%0,%1,%2,%3}, [%4];"
                             : "=f"(hv4.x), "=f"(hv4.y), "=f"(hv4.z), "=f"(hv4.w)
                             : "l"(src + tid) : "memory");
                *(float4*)shdst = hv4;
            }
            __syncthreads();
        }
        unsigned long long a0[4] = {0ull, 0ull, 0ull, 0ull};
        unsigned long long a1[4] = {0ull, 0ull, 0ull, 0ull};
#pragma unroll
        for (int i = 0; i < 8; i++) {
            const int coff = (((ks << 3) | (i ^ ks)) << 2);
#pragma unroll
            for (int b = 0; b < 4; b++) {
                ulonglong2 hv = *(const ulonglong2*)(sh_h + b * 256 + coff);
                a0[b] = fma2(wp0[2 * i],     hv.x, a0[b]);
                a0[b] = fma2(wp0[2 * i + 1], hv.y, a0[b]);
                a1[b] = fma2(wp1[2 * i],     hv.x, a1[b]);
                a1[b] = fma2(wp1[2 * i + 1], hv.y, a1[b]);
            }
        }
        float v0[4], v1[4];
#pragma unroll
        for (int b = 0; b < 4; b++) {
            float lo, hi;
            unpack2(a0[b], lo, hi); v0[b] = lo + hi;
            unpack2(a1[b], lo, hi); v1[b] = lo + hi;
        }
#pragma unroll
        for (int off = 1; off < 8; off <<= 1) {
#pragma unroll
            for (int b = 0; b < 4; b++) {
                v0[b] += __shfl_xor_sync(~0u, v0[b], off);
                v1[b] += __shfl_xor_sync(~0u, v1[b], off);
            }
        }
        if (ks == 0) {
            float4 f0 = make_float4(v0[0] + bh0, v0[1] + bh0, v0[2] + bh0, v0[3] + bh0);
            float4 f1 = make_float4(v1[0] + bh1, v1[1] + bh1, v1[2] + bh1, v1[3] + bh1);
            *(float4*)&sh_gate[rg * 8]     = f0;
            *(float4*)&sh_gate[rg * 8 + 4] = f1;
        }
        __syncthreads();
        if (tid < 128) {
            const float hgr = sh_gate[ju * 4 + bu];
            const float hgz = sh_gate[(32 + ju) * 4 + bu];
            const float hgn = sh_gate[(64 + ju) * 4 + bu];
            const float rr = 1.f / (1.f + __expf(-(xr + hgr)));
            const float zz = 1.f / (1.f + __expf(-(xz + hgz)));
            const float na = xn + rr * hgn;
            const float nn = 2.f / (1.f + __expf(-2.f * na)) - 1.f;
            const float hnew = (1.f - zz) * nn + zz * hreg;
            hreg = mk ? hnew : hreg;
            g_gru[((size_t)bglob * NS + s) * ND + dir * NH2 + jglob] = mk ? hreg : 0.f;
            if (t == NS - 1) {
                hid_out[bglob * ND + dir * NH2 + jglob] = hreg;
            } else {
                __stcg(hxg + (t & 1) * 1024 + bu * 256 + jglob, hreg);
            }
        }
        if (t < NS - 1) {
            __syncthreads();
            if (tid == 0) {
                __threadfence();
                unsigned nv = (unsigned)(t + 1);
                asm volatile("st.global.cg.u32 [%0], %1;"
                             :: "l"(myflag), "r"(nv) : "memory");
            }
        }
    }
}

// ------------------------- layernorm (optionally fused residual) ------------
__global__ void __launch_bounds__(128) ln_kernel(
    const float* __restrict__ x, const float* __restrict__ y,
    const float* __restrict__ gam, const float* __restrict__ bet,
    float* __restrict__ out)
{
    __shared__ float red[8];
    const int row = blockIdx.x;
    const int tid = threadIdx.x;
    float4 v = *(const float4*)(x + (size_t)row * ND + tid * 4);
    if (y) {
        float4 w = *(const float4*)(y + (size_t)row * ND + tid * 4);
        v.x += w.x; v.y += w.y; v.z += w.z; v.w += w.w;
    }
    float s1 = v.x + v.y + v.z + v.w;
    float s2 = v.x * v.x + v.y * v.y + v.z * v.z + v.w * v.w;
#pragma unroll
    for (int o = 16; o; o >>= 1) {
        s1 += __shfl_xor_sync(~0u, s1, o);
        s2 += __shfl_xor_sync(~0u, s2, o);
    }
    const int wid = tid >> 5;
    if ((tid & 31) == 0) { red[wid] = s1; red[wid + 4] = s2; }
    __syncthreads();
    s1 = red[0] + red[1] + red[2] + red[3];
    s2 = red[4] + red[5] + red[6] + red[7];
    const float mu = s1 * (1.f / ND);
    const float var = s2 * (1.f / ND) - mu * mu;
    const float rs = rsqrtf(var + 1e-5f);
    const float4 gv = *(const float4*)(gam + tid * 4);
    const float4 bv = *(const float4*)(bet + tid * 4);
    float4 o4;
    o4.x = (v.x - mu) * rs * gv.x + bv.x;
    o4.y = (v.y - mu) * rs * gv.y + bv.y;
    o4.z = (v.z - mu) * rs * gv.z + bv.z;
    o4.w = (v.w - mu) * rs * gv.w + bv.w;
    *(float4*)(out + (size_t)row * ND + tid * 4) = o4;
}

// ------------------------- launch -------------------------
extern "C" void kernel_launch(void* const* d_in, const int* in_sizes, int n_in,
                              void* d_out, int out_size)
{
    const float* splits = (const float*)d_in[0];
    const float* w_ih_f = (const float*)d_in[1];
    const float* w_hh_f = (const float*)d_in[2];
    const float* b_ih_f = (const float*)d_in[3];
    const float* b_hh_f = (const float*)d_in[4];
    const float* w_ih_b = (const float*)d_in[5];
    const float* w_hh_b = (const float*)d_in[6];
    const float* b_ih_b = (const float*)d_in[7];
    const float* b_hh_b = (const float*)d_in[8];
    const float* ln1_g  = (const float*)d_in[9];
    const float* ln1_b  = (const float*)d_in[10];
    const float* wq = (const float*)d_in[11];
    const float* bq = (const float*)d_in[12];
    const float* wk = (const float*)d_in[13];
    const float* bk = (const float*)d_in[14];
    const float* wv = (const float*)d_in[15];
    const float* bv = (const float*)d_in[16];
    const float* wo = (const float*)d_in[17];
    const float* bo = (const float*)d_in[18];
    const float* ln2_g = (const float*)d_in[19];
    const float* ln2_b = (const float*)d_in[20];
    const int* lengths = (const int*)d_in[21];
    const int* masks   = (const int*)d_in[22];
    float* out = (float*)d_out;

    float *xg, *gru, *ln1, *q, *k, *vt, *cc, *oo;
    cudaGetSymbolAddress((void**)&xg,  g_xg);
    cudaGetSymbolAddress((void**)&gru, g_gru);
    cudaGetSymbolAddress((void**)&ln1, g_ln1);
    cudaGetSymbolAddress((void**)&q,   g_q);
    cudaGetSymbolAddress((void**)&k,   g_k);
    cudaGetSymbolAddress((void**)&vt,  g_vt);
    cudaGetSymbolAddress((void**)&cc,  g_cc);
    cudaGetSymbolAddress((void**)&oo,  g_o);

    const int M = NB * NS;  // 16384
    const int ATTN_SMEM = ATTN_SMEM_FLOATS * 4;
    cudaFuncSetAttribute(attn_kernel, cudaFuncAttributeMaxDynamicSharedMemorySize, ATTN_SMEM);
    cudaFuncSetAttribute(gemm3, cudaFuncAttributeMaxDynamicSharedMemorySize, G3_SMEM);

    // GRU input projections — one launch, z = dir
    gemm3<<<dim3(6, 128, 2), 256, G3_SMEM>>>(
        splits, w_ih_f, w_ih_b, nullptr, b_ih_f, b_ih_b, nullptr,
        xg, xg + (size_t)M * NG3, nullptr, 0, 0, 0,
        M, NG3, ND, nullptr);
    // GRU recurrence (persistent, per-rank flag sync through L2)
    reset_kernel<<<16, 256>>>();
    gru_kernel<<<128, 384>>>(w_hh_f, w_hh_b, b_hh_f, b_hh_b, masks,
                             out + (size_t)NB * NS * ND);
    // LN1
    ln_kernel<<<M, 128>>>(gru, nullptr, ln1_g, ln1_b, ln1);
    // Q/K/V projections — one launch, z = {q, k, v}
    gemm3<<<dim3(4, 128, 3), 256, G3_SMEM>>>(
        ln1, wq, wk, wv, bq, bk, bv,
        q, k, vt, 1, 1, 2,
        M, ND, ND, nullptr);
    // fused attention: scores + masked online softmax + PV -> concat
    attn_kernel<<<dim3(4, 256), 256, ATTN_SMEM>>>(q, k, vt, cc, lengths);
    // out projection + row mask
    gemm3<<<dim3(4, 128, 1), 256, G3_SMEM>>>(
        cc, wo, nullptr, nullptr, bo, nullptr, nullptr,
        oo, nullptr, nullptr, 5, 5, 5,
        M, ND, ND, masks);
    // residual + LN2 -> final outputs
    ln_kernel<<<M, 128>>>(ln1, oo, ln2_g, ln2_b, out);
}